// round 1
// baseline (speedup 1.0000x reference)
#include <cuda_runtime.h>

// ---------------------------------------------------------------------------
// LMPNN fused kernel, round 1 (fp32 SIMT baseline)
//
// Stage 1: init   : g_aggr = 0.1*x ; out = 0
// Stage 2: scatter: g_aggr[dst] += (x[src] + rel_emb[rel]) * (1-2*neg)
// Stage 3: fused  : out = relu((g_aggr @ E^T) * scale + bias) @ E
//          (flash-style: never materializes the [4096 x 50000] score matrix)
// ---------------------------------------------------------------------------

#define DD 128
static constexpr int N_NODES = 4096;
static constexpr int N_EDGES = 262144;
static constexpr int N_ENT   = 50000;

static constexpr int BM = 64;   // nodes per block
static constexpr int BV = 64;   // entities per inner tile
static constexpr int NSPLIT = 7;                         // V-splits -> 448 blocks (~3 waves)
static constexpr int CHUNK  = (N_ENT + NSPLIT - 1) / NSPLIT;  // 7143
static constexpr int SPAD = 4;

static constexpr int SMEM_FLOATS = DD * BM      // AsT[k][m]
                                 + DD * BV      // EsT[k][v]
                                 + BV * DD      // Es2[v][d]
                                 + BM * (BV + SPAD);  // Ssm
static constexpr int SMEM_BYTES = SMEM_FLOATS * 4;    // 115,712 B -> dynamic smem

__device__ float g_aggr[N_NODES * DD];   // 2 MB scratch (allocation-free rule)

__device__ __forceinline__ void red_add_v4(float* p, float a, float b, float c, float d) {
    asm volatile("red.global.add.v4.f32 [%0], {%1, %2, %3, %4};"
                 :: "l"(p), "f"(a), "f"(b), "f"(c), "f"(d) : "memory");
}

// ---------------------------------------------------------------------------
__global__ void init_kernel(const float* __restrict__ x, float* __restrict__ out) {
    int i = blockIdx.x * blockDim.x + threadIdx.x;
    if (i < N_NODES * DD) {
        g_aggr[i] = 0.1f * x[i];
        out[i]    = 0.0f;
    }
}

// one warp per edge; lane owns 4 contiguous dims (float4)
__global__ void scatter_kernel(const float* __restrict__ x,
                               const int*   __restrict__ eidx,
                               const int*   __restrict__ rid,
                               const int*   __restrict__ neg,
                               const float* __restrict__ rel) {
    int gw   = (blockIdx.x * blockDim.x + threadIdx.x) >> 5;
    int lane = threadIdx.x & 31;
    if (gw >= N_EDGES) return;
    int src = eidx[gw];
    int dst = eidx[N_EDGES + gw];
    int r   = rid[gw];
    float coef = 1.0f - 2.0f * (float)neg[gw];

    float4 xv = ((const float4*)(x   + (size_t)src * DD))[lane];
    float4 rv = ((const float4*)(rel + (size_t)r   * DD))[lane];
    float4 m;
    m.x = (xv.x + rv.x) * coef;
    m.y = (xv.y + rv.y) * coef;
    m.z = (xv.z + rv.z) * coef;
    m.w = (xv.w + rv.w) * coef;
    red_add_v4(g_aggr + (size_t)dst * DD + lane * 4, m.x, m.y, m.z, m.w);
}

// ---------------------------------------------------------------------------
// Fused  relu((A E^T)*scale + bias) E  — fp32, register-tiled.
// Block: BM=64 nodes, loop entity chunk in BV=64 tiles. 256 threads.
// Phase 1: S[64x64] via 4x4 register tiles, reading transposed AsT/EsT
//          (float4 along the fast index -> conflict-free LDS).
// Phase 2: O[64x128] += S @ Es2, thread owns 4 rows x 8 cols.
// ---------------------------------------------------------------------------
__global__ void __launch_bounds__(256, 1)
gemm_fused(const float* __restrict__ eemb,
           const float* __restrict__ scale,
           const float* __restrict__ bias,
           float* __restrict__ out) {
    extern __shared__ float smem[];
    float (*AsT)[BM]        = (float (*)[BM])smem;
    float (*EsT)[BV]        = (float (*)[BV])(smem + DD * BM);
    float (*Es2)[DD]        = (float (*)[DD])(smem + DD * BM + DD * BV);
    float (*Ssm)[BV + SPAD] = (float (*)[BV + SPAD])(smem + DD * BM + DD * BV + BV * DD);

    const int tid  = threadIdx.x;
    const int mt   = blockIdx.x % (N_NODES / BM);
    const int sp   = blockIdx.x / (N_NODES / BM);
    const int m0   = mt * BM;
    const int vbeg = sp * CHUNK;
    const int vend = min(N_ENT, vbeg + CHUNK);

    // Load A tile transposed: AsT[k][m].  m-fast lane mapping -> conflict-free STS.
    for (int i = tid; i < BM * (DD / 4); i += 256) {
        int m  = i & (BM - 1);
        int k4 = i >> 6;
        float4 a = ((const float4*)(g_aggr + (size_t)(m0 + m) * DD))[k4];
        AsT[k4 * 4 + 0][m] = a.x;
        AsT[k4 * 4 + 1][m] = a.y;
        AsT[k4 * 4 + 2][m] = a.z;
        AsT[k4 * 4 + 3][m] = a.w;
    }

    const int sy = tid >> 4;   // 0..15 : S row group / O row group
    const int sx = tid & 15;   // 0..15 : S col group / O col group

    float Oacc[4][8];
    #pragma unroll
    for (int i = 0; i < 4; i++)
        #pragma unroll
        for (int j = 0; j < 8; j++) Oacc[i][j] = 0.0f;

    for (int v0 = vbeg; v0 < vend; v0 += BV) {
        __syncthreads();   // previous phase-2 done reading Es2/Ssm

        // Es2[v][d] : coalesced (k-fast) load+store
        for (int i = tid; i < BV * (DD / 4); i += 256) {
            int v  = i >> 5;
            int k4 = i & 31;
            int gv = v0 + v;
            float4 e = make_float4(0.f, 0.f, 0.f, 0.f);
            if (gv < vend) e = ((const float4*)(eemb + (size_t)gv * DD))[k4];
            ((float4*)&Es2[v][0])[k4] = e;
        }
        // EsT[k][v] : v-fast lane mapping so the transposed STS is conflict-free
        for (int i = tid; i < BV * (DD / 4); i += 256) {
            int v  = i & (BV - 1);
            int k4 = i >> 6;
            int gv = v0 + v;
            float4 e = make_float4(0.f, 0.f, 0.f, 0.f);
            if (gv < vend) e = ((const float4*)(eemb + (size_t)gv * DD))[k4];
            EsT[k4 * 4 + 0][v] = e.x;
            EsT[k4 * 4 + 1][v] = e.y;
            EsT[k4 * 4 + 2][v] = e.z;
            EsT[k4 * 4 + 3][v] = e.w;
        }
        __syncthreads();

        // Phase 1: S(4x4 per thread)
        float acc[4][4];
        #pragma unroll
        for (int i = 0; i < 4; i++)
            #pragma unroll
            for (int j = 0; j < 4; j++) acc[i][j] = 0.0f;

        #pragma unroll 4
        for (int k = 0; k < DD; k++) {
            float4 a = *(const float4*)&AsT[k][4 * sy];
            float4 b = *(const float4*)&EsT[k][4 * sx];
            float av[4] = {a.x, a.y, a.z, a.w};
            float bv[4] = {b.x, b.y, b.z, b.w};
            #pragma unroll
            for (int i = 0; i < 4; i++)
                #pragma unroll
                for (int j = 0; j < 4; j++)
                    acc[i][j] = fmaf(av[i], bv[j], acc[i][j]);
        }

        // relu(acc*scale + bias) -> Ssm
        #pragma unroll
        for (int j = 0; j < 4; j++) {
            int gv = v0 + 4 * sx + j;
            float sc = 0.f, bi = 0.f;
            if (gv < vend) { sc = scale[gv]; bi = bias[gv]; }
            #pragma unroll
            for (int i = 0; i < 4; i++) {
                float s = fmaxf(fmaf(acc[i][j], sc, bi), 0.0f);
                if (gv >= vend) s = 0.0f;     // padded rows contribute nothing
                Ssm[4 * sy + i][4 * sx + j] = s;
            }
        }
        __syncthreads();

        // Phase 2: O += S @ Es2
        #pragma unroll 4
        for (int v = 0; v < BV; v++) {
            float4 e0 = *(const float4*)&Es2[v][8 * sx];
            float4 e1 = *(const float4*)&Es2[v][8 * sx + 4];
            #pragma unroll
            for (int i = 0; i < 4; i++) {
                float s = Ssm[4 * sy + i][v];
                Oacc[i][0] = fmaf(s, e0.x, Oacc[i][0]);
                Oacc[i][1] = fmaf(s, e0.y, Oacc[i][1]);
                Oacc[i][2] = fmaf(s, e0.z, Oacc[i][2]);
                Oacc[i][3] = fmaf(s, e0.w, Oacc[i][3]);
                Oacc[i][4] = fmaf(s, e1.x, Oacc[i][4]);
                Oacc[i][5] = fmaf(s, e1.y, Oacc[i][5]);
                Oacc[i][6] = fmaf(s, e1.z, Oacc[i][6]);
                Oacc[i][7] = fmaf(s, e1.w, Oacc[i][7]);
            }
        }
    }

    // accumulate partial O into out (NSPLIT partials per node tile)
    #pragma unroll
    for (int i = 0; i < 4; i++) {
        float* p = out + (size_t)(m0 + 4 * sy + i) * DD + 8 * sx;
        red_add_v4(p,     Oacc[i][0], Oacc[i][1], Oacc[i][2], Oacc[i][3]);
        red_add_v4(p + 4, Oacc[i][4], Oacc[i][5], Oacc[i][6], Oacc[i][7]);
    }
}

// ---------------------------------------------------------------------------
extern "C" void kernel_launch(void* const* d_in, const int* in_sizes, int n_in,
                              void* d_out, int out_size) {
    const float* x     = (const float*)d_in[0];   // [4096,128] f32
    const int*   eidx  = (const int*)  d_in[1];   // [2,262144] i32
    const int*   rid   = (const int*)  d_in[2];   // [262144]   i32
    const int*   neg   = (const int*)  d_in[3];   // [262144]   i32
    const float* rel   = (const float*)d_in[4];   // [1000,128] f32
    const float* eemb  = (const float*)d_in[5];   // [50000,128] f32
    const float* scale = (const float*)d_in[6];   // [50000]    f32
    const float* bias  = (const float*)d_in[7];   // [50000]    f32
    float* out = (float*)d_out;                   // [4096,128] f32

    cudaFuncSetAttribute(gemm_fused, cudaFuncAttributeMaxDynamicSharedMemorySize, SMEM_BYTES);

    init_kernel<<<(N_NODES * DD + 255) / 256, 256>>>(x, out);
    scatter_kernel<<<N_EDGES * 32 / 256, 256>>>(x, eidx, rid, neg, rel);
    gemm_fused<<<(N_NODES / BM) * NSPLIT, 256, SMEM_BYTES>>>(eemb, scale, bias, out);
}

// round 4
// speedup vs baseline: 4.2300x; 4.2300x over previous
#include <cuda_runtime.h>
#include <cuda_bf16.h>
#include <cstdint>

// ---------------------------------------------------------------------------
// LMPNN round 4: bf16 hi/lo split (bf16x3) fused double-GEMM via mma.sync.
// R3 + fix: prefetch is issued AFTER the loop-top barrier, so cp.async never
// overwrites a buffer other warps are still reading (the R3 data race).
// ---------------------------------------------------------------------------

#define DD 128
static constexpr int N_NODES = 4096;
static constexpr int N_EDGES = 262144;
static constexpr int N_ENT   = 50000;

static constexpr int BM = 128;
static constexpr int BV = 64;
static constexpr int NVT = (N_ENT + BV - 1) / BV;        // 782
static constexpr int NSPLIT = 9;
static constexpr int TPS = (NVT + NSPLIT - 1) / NSPLIT;  // 87

__device__ float         g_aggr[N_NODES * DD];
__device__ __nv_bfloat16 g_Ehi[(size_t)N_ENT * DD];
__device__ __nv_bfloat16 g_Elo[(size_t)N_ENT * DD];

// ---- smem map (bytes) ------------------------------------------------------
static constexpr int SM_AHI = 0;          // 32768  A_hi [128m,128k]
static constexpr int SM_ALO = 32768;      // 32768
static constexpr int SM_EB  = 65536;      // 2 bufs x 33280
static constexpr int EB_HI  = 0;          // 16384  E [64v,128d]
static constexpr int EB_LO  = 16384;      // 16384
static constexpr int EB_SCB = 32768;      // 512 (64 scale f32 + 64 bias f32)
static constexpr int EB_STRIDE = 33280;
static constexpr int SM_SHI = 132096;     // 16384  S' [128m,64v]
static constexpr int SM_SLO = 148480;     // 16384
static constexpr int SMEM_BYTES = 164864;

// ---------------------------------------------------------------------------
__device__ __forceinline__ uint32_t s2u(const void* p) {
    uint32_t a;
    asm("{ .reg .u64 t; cvta.to.shared.u64 t, %1; cvt.u32.u64 %0, t; }" : "=r"(a) : "l"(p));
    return a;
}
// swizzled offsets: 16B chunks XOR'ed by (row & 7)
__device__ __forceinline__ uint32_t off128(int r, int c) {   // 128 bf16/row
    return (uint32_t)(r * 256) + ((((c >> 3) ^ (r & 7)) << 4) | ((c & 7) * 2));
}
__device__ __forceinline__ uint32_t off64(int r, int c) {    // 64 bf16/row
    return (uint32_t)(r * 128) + ((((c >> 3) ^ (r & 7)) << 4) | ((c & 7) * 2));
}
__device__ __forceinline__ void cpa16(uint32_t dst, const void* src, int srcsize) {
    asm volatile("cp.async.cg.shared.global [%0], [%1], 16, %2;"
                 :: "r"(dst), "l"(src), "r"(srcsize) : "memory");
}
__device__ __forceinline__ void cpa_commit() { asm volatile("cp.async.commit_group;" ::: "memory"); }
__device__ __forceinline__ void cpa_wait0()  { asm volatile("cp.async.wait_group 0;"  ::: "memory"); }

__device__ __forceinline__ void ldm4(uint32_t& r0, uint32_t& r1, uint32_t& r2, uint32_t& r3, uint32_t a) {
    asm volatile("ldmatrix.sync.aligned.m8n8.x4.shared.b16 {%0,%1,%2,%3}, [%4];"
                 : "=r"(r0), "=r"(r1), "=r"(r2), "=r"(r3) : "r"(a));
}
__device__ __forceinline__ void ldm4t(uint32_t& r0, uint32_t& r1, uint32_t& r2, uint32_t& r3, uint32_t a) {
    asm volatile("ldmatrix.sync.aligned.m8n8.x4.trans.shared.b16 {%0,%1,%2,%3}, [%4];"
                 : "=r"(r0), "=r"(r1), "=r"(r2), "=r"(r3) : "r"(a));
}
__device__ __forceinline__ void mma16816(float* d, const uint32_t* a, const uint32_t* b) {
    asm volatile("mma.sync.aligned.m16n8k16.row.col.f32.bf16.bf16.f32 "
                 "{%0,%1,%2,%3}, {%4,%5,%6,%7}, {%8,%9}, {%0,%1,%2,%3};"
                 : "+f"(d[0]), "+f"(d[1]), "+f"(d[2]), "+f"(d[3])
                 : "r"(a[0]), "r"(a[1]), "r"(a[2]), "r"(a[3]), "r"(b[0]), "r"(b[1]));
}
__device__ __forceinline__ void red_add_v2(float* p, float a, float b) {
    asm volatile("red.global.add.v2.f32 [%0], {%1, %2};" :: "l"(p), "f"(a), "f"(b) : "memory");
}
__device__ __forceinline__ void red_add_v4(float* p, float a, float b, float c, float d) {
    asm volatile("red.global.add.v4.f32 [%0], {%1, %2, %3, %4};"
                 :: "l"(p), "f"(a), "f"(b), "f"(c), "f"(d) : "memory");
}
__device__ __forceinline__ void split2(float a, float b, uint32_t& hp, uint32_t& lp) {
    __nv_bfloat16 ha = __float2bfloat16(a), hb = __float2bfloat16(b);
    __nv_bfloat16 la = __float2bfloat16(a - __bfloat162float(ha));
    __nv_bfloat16 lb = __float2bfloat16(b - __bfloat162float(hb));
    hp = (uint32_t)__bfloat16_as_ushort(ha) | ((uint32_t)__bfloat16_as_ushort(hb) << 16);
    lp = (uint32_t)__bfloat16_as_ushort(la) | ((uint32_t)__bfloat16_as_ushort(lb) << 16);
}

// ---------------------------------------------------------------------------
__global__ void init_kernel(const float* __restrict__ x, float* __restrict__ out) {
    int i = blockIdx.x * blockDim.x + threadIdx.x;
    if (i < N_NODES * DD) { g_aggr[i] = 0.1f * x[i]; out[i] = 0.0f; }
}

__global__ void scatter_kernel(const float* __restrict__ x, const int* __restrict__ eidx,
                               const int* __restrict__ rid, const int* __restrict__ neg,
                               const float* __restrict__ rel) {
    int gw = (blockIdx.x * blockDim.x + threadIdx.x) >> 5;
    int lane = threadIdx.x & 31;
    if (gw >= N_EDGES) return;
    int src = eidx[gw], dst = eidx[N_EDGES + gw], r = rid[gw];
    float coef = 1.0f - 2.0f * (float)neg[gw];
    float4 xv = ((const float4*)(x + (size_t)src * DD))[lane];
    float4 rv = ((const float4*)(rel + (size_t)r * DD))[lane];
    red_add_v4(g_aggr + (size_t)dst * DD + lane * 4,
               (xv.x + rv.x) * coef, (xv.y + rv.y) * coef,
               (xv.z + rv.z) * coef, (xv.w + rv.w) * coef);
}

__global__ void prep_kernel(const float* __restrict__ eemb) {
    int i = blockIdx.x * blockDim.x + threadIdx.x;    // over N_ENT*64 float2
    if (i >= N_ENT * (DD / 2)) return;
    float2 v = ((const float2*)eemb)[i];
    uint32_t hp, lp; split2(v.x, v.y, hp, lp);
    ((uint32_t*)g_Ehi)[i] = hp;
    ((uint32_t*)g_Elo)[i] = lp;
}

// ---------------------------------------------------------------------------
__global__ void __launch_bounds__(256, 1)
gemm_fused(const float* __restrict__ scal, const float* __restrict__ bias,
           float* __restrict__ out) {
    extern __shared__ char smem[];
    const uint32_t sb = s2u(smem);
    const int tid = threadIdx.x, wid = tid >> 5, lane = tid & 31;
    const int mt = blockIdx.x & 31, sp = blockIdx.x >> 5;
    const int m0 = mt * BM;
    const int t0 = sp * TPS, t1 = min(NVT, t0 + TPS);
    if (t0 >= t1) return;

    const int wm = (wid >> 1) * 32;        // warp m-offset (both GEMMs)
    const int wsel = wid & 1;              // GEMM1: v half; GEMM2: d half

    // ---- A tile: g_aggr f32 -> hi/lo bf16, swizzled ----
    for (int i = tid; i < BM * (DD / 4); i += 256) {
        int m = i >> 5, k = (i & 31) * 4;
        float4 a = *(const float4*)(g_aggr + (size_t)(m0 + m) * DD + k);
        uint32_t h01, l01, h23, l23;
        split2(a.x, a.y, h01, l01);
        split2(a.z, a.w, h23, l23);
        uint32_t o0 = off128(m, k), o1 = off128(m, k + 2);
        *(uint32_t*)(smem + SM_AHI + o0) = h01; *(uint32_t*)(smem + SM_AHI + o1) = h23;
        *(uint32_t*)(smem + SM_ALO + o0) = l01; *(uint32_t*)(smem + SM_ALO + o1) = l23;
    }

    auto load_tiles = [&](int t, int b) {
        const int v0 = t * BV;
        const uint32_t eb = sb + SM_EB + b * EB_STRIDE;
        for (int i = tid; i < 1024; i += 256) {     // E [64v,128d] hi/lo, 16B chunks
            int v = i >> 4, dg = (i & 15) * 8;
            int gv = v0 + v;
            uint32_t o = off128(v, dg);
            int sz = (gv < N_ENT) ? 16 : 0;
            const void* pH = sz ? (const void*)(g_Ehi + (size_t)gv * DD + dg) : (const void*)g_Ehi;
            const void* pL = sz ? (const void*)(g_Elo + (size_t)gv * DD + dg) : (const void*)g_Elo;
            cpa16(eb + EB_HI + o, pH, sz);
            cpa16(eb + EB_LO + o, pL, sz);
        }
        if (tid < 32) {                              // 64 scale + 64 bias f32
            int half = tid >> 4, g = tid & 15;
            int gv = v0 + g * 4;
            int rem = N_ENT - gv;
            int sz = rem >= 4 ? 16 : (rem > 0 ? rem * 4 : 0);
            const float* src = half ? bias : scal;
            const void* p = sz ? (const void*)(src + gv) : (const void*)src;
            cpa16(eb + EB_SCB + half * 256 + g * 16, p, sz);
        }
    };

    float accO[2][8][4];
    #pragma unroll
    for (int mi = 0; mi < 2; mi++)
        #pragma unroll
        for (int nt = 0; nt < 8; nt++)
            #pragma unroll
            for (int q = 0; q < 4; q++) accO[mi][nt][q] = 0.0f;

    load_tiles(t0, 0);
    cpa_commit();

    // per-lane ldmatrix row/col pieces (constant across loop)
    const int lr16 = lane & 15;            // row within 16
    const int lc8  = (lane >> 4) << 3;     // +8 col for upper half-warp
    const int lrB  = (lane & 7) | ((lane & 16) >> 1);  // B non-trans row
    const int lcB  = lane & 8;                          // B non-trans col sel

    for (int t = t0; t < t1; ++t) {
        const int buf = (t - t0) & 1;
        const uint32_t eb = sb + SM_EB + buf * EB_STRIDE;

        cpa_wait0();           // tile t landed (this thread's copies)
        __syncthreads();       // ...visible to all; all warps done with buf^1
        if (t + 1 < t1) { load_tiles(t + 1, buf ^ 1); cpa_commit(); }

        // ---------------- GEMM1: S[128m x 64v] = A . E^T (3 split passes) ----
        float accS[2][4][4];
        #pragma unroll
        for (int mi = 0; mi < 2; mi++)
            #pragma unroll
            for (int nt = 0; nt < 4; nt++)
                #pragma unroll
                for (int q = 0; q < 4; q++) accS[mi][nt][q] = 0.0f;

        #pragma unroll
        for (int ks = 0; ks < 8; ks++) {
            const int k0 = ks * 16;
            uint32_t aH[2][4], aL[2][4];
            #pragma unroll
            for (int mi = 0; mi < 2; mi++) {
                uint32_t o = off128(wm + mi * 16 + lr16, k0 + lc8);
                ldm4(aH[mi][0], aH[mi][1], aH[mi][2], aH[mi][3], sb + SM_AHI + o);
                ldm4(aL[mi][0], aL[mi][1], aL[mi][2], aL[mi][3], sb + SM_ALO + o);
            }
            uint32_t bH[4][2], bL[4][2];
            #pragma unroll
            for (int ng = 0; ng < 2; ng++) {
                uint32_t o = off128(wsel * 32 + ng * 16 + lrB, k0 + lcB);
                uint32_t r0, r1, r2, r3;
                ldm4(r0, r1, r2, r3, eb + EB_HI + o);
                bH[ng * 2][0] = r0; bH[ng * 2][1] = r1;
                bH[ng * 2 + 1][0] = r2; bH[ng * 2 + 1][1] = r3;
                ldm4(r0, r1, r2, r3, eb + EB_LO + o);
                bL[ng * 2][0] = r0; bL[ng * 2][1] = r1;
                bL[ng * 2 + 1][0] = r2; bL[ng * 2 + 1][1] = r3;
            }
            #pragma unroll
            for (int mi = 0; mi < 2; mi++)
                #pragma unroll
                for (int nt = 0; nt < 4; nt++) {
                    mma16816(accS[mi][nt], aH[mi], bH[nt]);
                    mma16816(accS[mi][nt], aH[mi], bL[nt]);
                    mma16816(accS[mi][nt], aL[mi], bH[nt]);
                }
        }

        // ---------------- epilogue: relu(scale*s+bias), split -> S' smem -----
        {
            const float* sc = (const float*)(smem + SM_EB + buf * EB_STRIDE + EB_SCB);
            const float* bi = sc + 64;
            #pragma unroll
            for (int mi = 0; mi < 2; mi++) {
                const int r0 = wm + mi * 16 + (lane >> 2);
                #pragma unroll
                for (int nt = 0; nt < 4; nt++) {
                    const int c = wsel * 32 + nt * 8 + (lane & 3) * 2;
                    float s0 = sc[c], s1 = sc[c + 1], b0 = bi[c], b1 = bi[c + 1];
                    float v00 = fmaxf(fmaf(accS[mi][nt][0], s0, b0), 0.f);
                    float v01 = fmaxf(fmaf(accS[mi][nt][1], s1, b1), 0.f);
                    float v10 = fmaxf(fmaf(accS[mi][nt][2], s0, b0), 0.f);
                    float v11 = fmaxf(fmaf(accS[mi][nt][3], s1, b1), 0.f);
                    uint32_t hp, lp;
                    split2(v00, v01, hp, lp);
                    uint32_t o = off64(r0, c);
                    *(uint32_t*)(smem + SM_SHI + o) = hp;
                    *(uint32_t*)(smem + SM_SLO + o) = lp;
                    split2(v10, v11, hp, lp);
                    o = off64(r0 + 8, c);
                    *(uint32_t*)(smem + SM_SHI + o) = hp;
                    *(uint32_t*)(smem + SM_SLO + o) = lp;
                }
            }
        }
        __syncthreads();

        // ---------------- GEMM2: O[128m x 128d] += S' . E (3 split passes) ---
        #pragma unroll
        for (int ks = 0; ks < 4; ks++) {
            const int k0 = ks * 16;
            uint32_t aH[2][4], aL[2][4];
            #pragma unroll
            for (int mi = 0; mi < 2; mi++) {
                uint32_t o = off64(wm + mi * 16 + lr16, k0 + lc8);
                ldm4(aH[mi][0], aH[mi][1], aH[mi][2], aH[mi][3], sb + SM_SHI + o);
                ldm4(aL[mi][0], aL[mi][1], aL[mi][2], aL[mi][3], sb + SM_SLO + o);
            }
            uint32_t bH[8][2], bL[8][2];
            #pragma unroll
            for (int ng = 0; ng < 4; ng++) {
                uint32_t o = off128(k0 + lr16, wsel * 64 + ng * 16 + lc8);
                uint32_t r0, r1, r2, r3;
                ldm4t(r0, r1, r2, r3, eb + EB_HI + o);
                bH[ng * 2][0] = r0; bH[ng * 2][1] = r1;
                bH[ng * 2 + 1][0] = r2; bH[ng * 2 + 1][1] = r3;
                ldm4t(r0, r1, r2, r3, eb + EB_LO + o);
                bL[ng * 2][0] = r0; bL[ng * 2][1] = r1;
                bL[ng * 2 + 1][0] = r2; bL[ng * 2 + 1][1] = r3;
            }
            #pragma unroll
            for (int mi = 0; mi < 2; mi++)
                #pragma unroll
                for (int nt = 0; nt < 8; nt++) {
                    mma16816(accO[mi][nt], aH[mi], bH[nt]);
                    mma16816(accO[mi][nt], aH[mi], bL[nt]);
                    mma16816(accO[mi][nt], aL[mi], bH[nt]);
                }
        }
    }

    // ---- flush O to out (+= across splits) ----
    #pragma unroll
    for (int mi = 0; mi < 2; mi++) {
        const int r0 = m0 + wm + mi * 16 + (lane >> 2);
        #pragma unroll
        for (int nt = 0; nt < 8; nt++) {
            const int c = wsel * 64 + nt * 8 + (lane & 3) * 2;
            red_add_v2(out + (size_t)r0 * DD + c,       accO[mi][nt][0], accO[mi][nt][1]);
            red_add_v2(out + (size_t)(r0 + 8) * DD + c, accO[mi][nt][2], accO[mi][nt][3]);
        }
    }
}

// ---------------------------------------------------------------------------
extern "C" void kernel_launch(void* const* d_in, const int* in_sizes, int n_in,
                              void* d_out, int out_size) {
    const float* x     = (const float*)d_in[0];
    const int*   eidx  = (const int*)  d_in[1];
    const int*   rid   = (const int*)  d_in[2];
    const int*   neg   = (const int*)  d_in[3];
    const float* rel   = (const float*)d_in[4];
    const float* eemb  = (const float*)d_in[5];
    const float* scale = (const float*)d_in[6];
    const float* bias  = (const float*)d_in[7];
    float* out = (float*)d_out;

    cudaFuncSetAttribute(gemm_fused, cudaFuncAttributeMaxDynamicSharedMemorySize, SMEM_BYTES);

    prep_kernel<<<(N_ENT * (DD / 2) + 255) / 256, 256>>>(eemb);
    init_kernel<<<(N_NODES * DD + 255) / 256, 256>>>(x, out);
    scatter_kernel<<<N_EDGES * 32 / 256, 256>>>(x, eidx, rid, neg, rel);
    gemm_fused<<<32 * NSPLIT, 256, SMEM_BYTES>>>(scale, bias, out);
}

// round 5
// speedup vs baseline: 4.2765x; 1.0110x over previous
#include <cuda_runtime.h>
#include <cuda_bf16.h>
#include <cstdint>

// ---------------------------------------------------------------------------
// LMPNN round 5: bf16x3 fused double-GEMM via mma.sync, 2 CTAs/SM.
// BM 128->64, scale/bias via LDG (smem 114,688B) so two CTAs co-reside and
// one CTA's MMAs fill the other's epilogue/barrier bubbles.
// ---------------------------------------------------------------------------

#define DD 128
static constexpr int N_NODES = 4096;
static constexpr int N_EDGES = 262144;
static constexpr int N_ENT   = 50000;

static constexpr int BM = 64;
static constexpr int BV = 64;
static constexpr int NVT = (N_ENT + BV - 1) / BV;        // 782
static constexpr int NSPLIT = 9;
static constexpr int TPS = (NVT + NSPLIT - 1) / NSPLIT;  // 87
static constexpr int MTILES = N_NODES / BM;              // 64

__device__ float         g_aggr[N_NODES * DD];
__device__ __nv_bfloat16 g_Ehi[(size_t)N_ENT * DD];
__device__ __nv_bfloat16 g_Elo[(size_t)N_ENT * DD];

// ---- smem map (bytes) ------------------------------------------------------
static constexpr int SM_AHI = 0;          // 16384  A_hi [64m,128k]
static constexpr int SM_ALO = 16384;      // 16384
static constexpr int SM_EB  = 32768;      // 2 bufs x 32768
static constexpr int EB_HI  = 0;          // 16384  E [64v,128d]
static constexpr int EB_LO  = 16384;      // 16384
static constexpr int EB_STRIDE = 32768;
static constexpr int SM_SHI = 98304;      // 8192   S' [64m,64v]
static constexpr int SM_SLO = 106496;     // 8192
static constexpr int SMEM_BYTES = 114688; // 2 CTAs x 114688 = 229376 <= 228KB SM

// ---------------------------------------------------------------------------
__device__ __forceinline__ uint32_t s2u(const void* p) {
    uint32_t a;
    asm("{ .reg .u64 t; cvta.to.shared.u64 t, %1; cvt.u32.u64 %0, t; }" : "=r"(a) : "l"(p));
    return a;
}
// swizzled offsets: 16B chunks XOR'ed by (row & 7)
__device__ __forceinline__ uint32_t off128(int r, int c) {   // 128 bf16/row
    return (uint32_t)(r * 256) + ((((c >> 3) ^ (r & 7)) << 4) | ((c & 7) * 2));
}
__device__ __forceinline__ uint32_t off64(int r, int c) {    // 64 bf16/row
    return (uint32_t)(r * 128) + ((((c >> 3) ^ (r & 7)) << 4) | ((c & 7) * 2));
}
__device__ __forceinline__ void cpa16(uint32_t dst, const void* src, int srcsize) {
    asm volatile("cp.async.cg.shared.global [%0], [%1], 16, %2;"
                 :: "r"(dst), "l"(src), "r"(srcsize) : "memory");
}
__device__ __forceinline__ void cpa_commit() { asm volatile("cp.async.commit_group;" ::: "memory"); }
__device__ __forceinline__ void cpa_wait0()  { asm volatile("cp.async.wait_group 0;"  ::: "memory"); }

__device__ __forceinline__ void ldm4(uint32_t& r0, uint32_t& r1, uint32_t& r2, uint32_t& r3, uint32_t a) {
    asm volatile("ldmatrix.sync.aligned.m8n8.x4.shared.b16 {%0,%1,%2,%3}, [%4];"
                 : "=r"(r0), "=r"(r1), "=r"(r2), "=r"(r3) : "r"(a));
}
__device__ __forceinline__ void ldm4t(uint32_t& r0, uint32_t& r1, uint32_t& r2, uint32_t& r3, uint32_t a) {
    asm volatile("ldmatrix.sync.aligned.m8n8.x4.trans.shared.b16 {%0,%1,%2,%3}, [%4];"
                 : "=r"(r0), "=r"(r1), "=r"(r2), "=r"(r3) : "r"(a));
}
__device__ __forceinline__ void mma16816(float* d, const uint32_t* a, const uint32_t* b) {
    asm volatile("mma.sync.aligned.m16n8k16.row.col.f32.bf16.bf16.f32 "
                 "{%0,%1,%2,%3}, {%4,%5,%6,%7}, {%8,%9}, {%0,%1,%2,%3};"
                 : "+f"(d[0]), "+f"(d[1]), "+f"(d[2]), "+f"(d[3])
                 : "r"(a[0]), "r"(a[1]), "r"(a[2]), "r"(a[3]), "r"(b[0]), "r"(b[1]));
}
__device__ __forceinline__ void red_add_v2(float* p, float a, float b) {
    asm volatile("red.global.add.v2.f32 [%0], {%1, %2};" :: "l"(p), "f"(a), "f"(b) : "memory");
}
__device__ __forceinline__ void red_add_v4(float* p, float a, float b, float c, float d) {
    asm volatile("red.global.add.v4.f32 [%0], {%1, %2, %3, %4};"
                 :: "l"(p), "f"(a), "f"(b), "f"(c), "f"(d) : "memory");
}
__device__ __forceinline__ void split2(float a, float b, uint32_t& hp, uint32_t& lp) {
    __nv_bfloat16 ha = __float2bfloat16(a), hb = __float2bfloat16(b);
    __nv_bfloat16 la = __float2bfloat16(a - __bfloat162float(ha));
    __nv_bfloat16 lb = __float2bfloat16(b - __bfloat162float(hb));
    hp = (uint32_t)__bfloat16_as_ushort(ha) | ((uint32_t)__bfloat16_as_ushort(hb) << 16);
    lp = (uint32_t)__bfloat16_as_ushort(la) | ((uint32_t)__bfloat16_as_ushort(lb) << 16);
}

// ---------------------------------------------------------------------------
__global__ void init_kernel(const float* __restrict__ x, float* __restrict__ out) {
    int i = blockIdx.x * blockDim.x + threadIdx.x;
    if (i < N_NODES * DD) { g_aggr[i] = 0.1f * x[i]; out[i] = 0.0f; }
}

__global__ void scatter_kernel(const float* __restrict__ x, const int* __restrict__ eidx,
                               const int* __restrict__ rid, const int* __restrict__ neg,
                               const float* __restrict__ rel) {
    int gw = (blockIdx.x * blockDim.x + threadIdx.x) >> 5;
    int lane = threadIdx.x & 31;
    if (gw >= N_EDGES) return;
    int src = eidx[gw], dst = eidx[N_EDGES + gw], r = rid[gw];
    float coef = 1.0f - 2.0f * (float)neg[gw];
    float4 xv = ((const float4*)(x + (size_t)src * DD))[lane];
    float4 rv = ((const float4*)(rel + (size_t)r * DD))[lane];
    red_add_v4(g_aggr + (size_t)dst * DD + lane * 4,
               (xv.x + rv.x) * coef, (xv.y + rv.y) * coef,
               (xv.z + rv.z) * coef, (xv.w + rv.w) * coef);
}

__global__ void prep_kernel(const float* __restrict__ eemb) {
    int i = blockIdx.x * blockDim.x + threadIdx.x;    // over N_ENT*64 float2
    if (i >= N_ENT * (DD / 2)) return;
    float2 v = ((const float2*)eemb)[i];
    uint32_t hp, lp; split2(v.x, v.y, hp, lp);
    ((uint32_t*)g_Ehi)[i] = hp;
    ((uint32_t*)g_Elo)[i] = lp;
}

// ---------------------------------------------------------------------------
__global__ void __launch_bounds__(256, 2)
gemm_fused(const float* __restrict__ scal, const float* __restrict__ bias,
           float* __restrict__ out) {
    extern __shared__ char smem[];
    const uint32_t sb = s2u(smem);
    const int tid = threadIdx.x, wid = tid >> 5, lane = tid & 31;
    const int mt = blockIdx.x & (MTILES - 1), sp = blockIdx.x / MTILES;
    const int m0 = mt * BM;
    const int t0 = sp * TPS, t1 = min(NVT, t0 + TPS);
    if (t0 >= t1) return;

    const int wm = (wid >> 1) * 16;        // warp m-offset: 4 warp-rows x 16
    const int wsel = wid & 1;              // GEMM1: v half; GEMM2: d half

    // ---- A tile: g_aggr f32 -> hi/lo bf16, swizzled ----
    for (int i = tid; i < BM * (DD / 4); i += 256) {
        int m = i >> 5, k = (i & 31) * 4;
        float4 a = *(const float4*)(g_aggr + (size_t)(m0 + m) * DD + k);
        uint32_t h01, l01, h23, l23;
        split2(a.x, a.y, h01, l01);
        split2(a.z, a.w, h23, l23);
        uint32_t o0 = off128(m, k), o1 = off128(m, k + 2);
        *(uint32_t*)(smem + SM_AHI + o0) = h01; *(uint32_t*)(smem + SM_AHI + o1) = h23;
        *(uint32_t*)(smem + SM_ALO + o0) = l01; *(uint32_t*)(smem + SM_ALO + o1) = l23;
    }

    auto load_tiles = [&](int t, int b) {
        const int v0 = t * BV;
        const uint32_t eb = sb + SM_EB + b * EB_STRIDE;
        for (int i = tid; i < 1024; i += 256) {     // E [64v,128d] hi/lo, 16B chunks
            int v = i >> 4, dg = (i & 15) * 8;
            int gv = v0 + v;
            uint32_t o = off128(v, dg);
            int sz = (gv < N_ENT) ? 16 : 0;
            const void* pH = sz ? (const void*)(g_Ehi + (size_t)gv * DD + dg) : (const void*)g_Ehi;
            const void* pL = sz ? (const void*)(g_Elo + (size_t)gv * DD + dg) : (const void*)g_Elo;
            cpa16(eb + EB_HI + o, pH, sz);
            cpa16(eb + EB_LO + o, pL, sz);
        }
    };

    float accO[8][4];
    #pragma unroll
    for (int nt = 0; nt < 8; nt++)
        #pragma unroll
        for (int q = 0; q < 4; q++) accO[nt][q] = 0.0f;

    load_tiles(t0, 0);
    cpa_commit();

    // per-lane ldmatrix row/col pieces (constant across loop)
    const int lr16 = lane & 15;            // row within 16
    const int lc8  = (lane >> 4) << 3;     // +8 col for upper half-warp
    const int lrB  = (lane & 7) | ((lane & 16) >> 1);  // B non-trans row
    const int lcB  = lane & 8;                          // B non-trans col sel
    const int ce   = (lane & 3) * 2;       // epilogue col pair base

    for (int t = t0; t < t1; ++t) {
        const int buf = (t - t0) & 1;
        const uint32_t eb = sb + SM_EB + buf * EB_STRIDE;

        // prefetch scale/bias for this tile's columns (L2-resident)
        float2 scv[4], biv[4];
        {
            const int v0t = t * BV;
            #pragma unroll
            for (int nt = 0; nt < 4; nt++) {
                int gc = v0t + wsel * 32 + nt * 8 + ce;
                if (gc + 1 < N_ENT) {
                    scv[nt] = __ldg((const float2*)(scal + gc));
                    biv[nt] = __ldg((const float2*)(bias + gc));
                } else {
                    scv[nt].x = (gc < N_ENT) ? __ldg(scal + gc) : 0.f;
                    scv[nt].y = 0.f;
                    biv[nt].x = (gc < N_ENT) ? __ldg(bias + gc) : 0.f;
                    biv[nt].y = 0.f;
                }
            }
        }

        cpa_wait0();           // tile t landed (this thread's copies)
        __syncthreads();       // ...visible to all; all warps done with buf^1
        if (t + 1 < t1) { load_tiles(t + 1, buf ^ 1); cpa_commit(); }

        // ---------------- GEMM1: S[64m x 64v] = A . E^T (3 split passes) -----
        float accS[4][4];
        #pragma unroll
        for (int nt = 0; nt < 4; nt++)
            #pragma unroll
            for (int q = 0; q < 4; q++) accS[nt][q] = 0.0f;

        #pragma unroll
        for (int ks = 0; ks < 8; ks++) {
            const int k0 = ks * 16;
            uint32_t aH[4], aL[4];
            {
                uint32_t o = off128(wm + lr16, k0 + lc8);
                ldm4(aH[0], aH[1], aH[2], aH[3], sb + SM_AHI + o);
                ldm4(aL[0], aL[1], aL[2], aL[3], sb + SM_ALO + o);
            }
            uint32_t bH[4][2], bL[4][2];
            #pragma unroll
            for (int ng = 0; ng < 2; ng++) {
                uint32_t o = off128(wsel * 32 + ng * 16 + lrB, k0 + lcB);
                uint32_t r0, r1, r2, r3;
                ldm4(r0, r1, r2, r3, eb + EB_HI + o);
                bH[ng * 2][0] = r0; bH[ng * 2][1] = r1;
                bH[ng * 2 + 1][0] = r2; bH[ng * 2 + 1][1] = r3;
                ldm4(r0, r1, r2, r3, eb + EB_LO + o);
                bL[ng * 2][0] = r0; bL[ng * 2][1] = r1;
                bL[ng * 2 + 1][0] = r2; bL[ng * 2 + 1][1] = r3;
            }
            #pragma unroll
            for (int nt = 0; nt < 4; nt++) {
                mma16816(accS[nt], aH, bH[nt]);
                mma16816(accS[nt], aH, bL[nt]);
                mma16816(accS[nt], aL, bH[nt]);
            }
        }

        // ---------------- epilogue: relu(scale*s+bias), split -> S' smem -----
        {
            const int r0 = wm + (lane >> 2);
            #pragma unroll
            for (int nt = 0; nt < 4; nt++) {
                const int c = wsel * 32 + nt * 8 + ce;
                float s0 = scv[nt].x, s1 = scv[nt].y, b0 = biv[nt].x, b1 = biv[nt].y;
                float v00 = fmaxf(fmaf(accS[nt][0], s0, b0), 0.f);
                float v01 = fmaxf(fmaf(accS[nt][1], s1, b1), 0.f);
                float v10 = fmaxf(fmaf(accS[nt][2], s0, b0), 0.f);
                float v11 = fmaxf(fmaf(accS[nt][3], s1, b1), 0.f);
                uint32_t hp, lp;
                split2(v00, v01, hp, lp);
                uint32_t o = off64(r0, c);
                *(uint32_t*)(smem + SM_SHI + o) = hp;
                *(uint32_t*)(smem + SM_SLO + o) = lp;
                split2(v10, v11, hp, lp);
                o = off64(r0 + 8, c);
                *(uint32_t*)(smem + SM_SHI + o) = hp;
                *(uint32_t*)(smem + SM_SLO + o) = lp;
            }
        }
        __syncthreads();

        // ---------------- GEMM2: O[64m x 128d] += S' . E (3 split passes) ----
        #pragma unroll
        for (int ks = 0; ks < 4; ks++) {
            const int k0 = ks * 16;
            uint32_t aH[4], aL[4];
            {
                uint32_t o = off64(wm + lr16, k0 + lc8);
                ldm4(aH[0], aH[1], aH[2], aH[3], sb + SM_SHI + o);
                ldm4(aL[0], aL[1], aL[2], aL[3], sb + SM_SLO + o);
            }
            #pragma unroll
            for (int half = 0; half < 2; half++) {      // nt 0-3, then 4-7
                uint32_t bH[4][2], bL[4][2];
                #pragma unroll
                for (int ng = 0; ng < 2; ng++) {
                    uint32_t o = off128(k0 + lr16, wsel * 64 + half * 32 + ng * 16 + lc8);
                    uint32_t r0, r1, r2, r3;
                    ldm4t(r0, r1, r2, r3, eb + EB_HI + o);
                    bH[ng * 2][0] = r0; bH[ng * 2][1] = r1;
                    bH[ng * 2 + 1][0] = r2; bH[ng * 2 + 1][1] = r3;
                    ldm4t(r0, r1, r2, r3, eb + EB_LO + o);
                    bL[ng * 2][0] = r0; bL[ng * 2][1] = r1;
                    bL[ng * 2 + 1][0] = r2; bL[ng * 2 + 1][1] = r3;
                }
                #pragma unroll
                for (int ng = 0; ng < 4; ng++) {
                    float* d = accO[half * 4 + ng];
                    mma16816(d, aH, bH[ng]);
                    mma16816(d, aH, bL[ng]);
                    mma16816(d, aL, bH[ng]);
                }
            }
        }
    }

    // ---- flush O to out (+= across splits) ----
    {
        const int r0 = m0 + wm + (lane >> 2);
        #pragma unroll
        for (int nt = 0; nt < 8; nt++) {
            const int c = wsel * 64 + nt * 8 + ce;
            red_add_v2(out + (size_t)r0 * DD + c,       accO[nt][0], accO[nt][1]);
            red_add_v2(out + (size_t)(r0 + 8) * DD + c, accO[nt][2], accO[nt][3]);
        }
    }
}

// ---------------------------------------------------------------------------
extern "C" void kernel_launch(void* const* d_in, const int* in_sizes, int n_in,
                              void* d_out, int out_size) {
    const float* x     = (const float*)d_in[0];
    const int*   eidx  = (const int*)  d_in[1];
    const int*   rid   = (const int*)  d_in[2];
    const int*   neg   = (const int*)  d_in[3];
    const float* rel   = (const float*)d_in[4];
    const float* eemb  = (const float*)d_in[5];
    const float* scale = (const float*)d_in[6];
    const float* bias  = (const float*)d_in[7];
    float* out = (float*)d_out;

    cudaFuncSetAttribute(gemm_fused, cudaFuncAttributeMaxDynamicSharedMemorySize, SMEM_BYTES);

    prep_kernel<<<(N_ENT * (DD / 2) + 255) / 256, 256>>>(eemb);
    init_kernel<<<(N_NODES * DD + 255) / 256, 256>>>(x, out);
    scatter_kernel<<<N_EDGES * 32 / 256, 256>>>(x, eidx, rid, neg, rel);
    gemm_fused<<<MTILES * NSPLIT, 256, SMEM_BYTES>>>(scale, bias, out);
}

// round 6
// speedup vs baseline: 4.7322x; 1.1066x over previous
#include <cuda_runtime.h>
#include <cuda_bf16.h>
#include <cstdint>

// ---------------------------------------------------------------------------
// LMPNN round 6: bf16x3 fused double-GEMM, 128-thread CTAs, 2 CTAs/SM,
// 32x32 / 32x64 warp tiles (MMA/LDSM ratio 3.0 / 4.0), pairwise named
// barriers between epilogue and GEMM2, bf16x2 cvt epilogue.
// ---------------------------------------------------------------------------

#define DD 128
static constexpr int N_NODES = 4096;
static constexpr int N_EDGES = 262144;
static constexpr int N_ENT   = 50000;

static constexpr int BM = 64;
static constexpr int BV = 64;
static constexpr int NVT = (N_ENT + BV - 1) / BV;        // 782
static constexpr int NSPLIT = 9;
static constexpr int TPS = (NVT + NSPLIT - 1) / NSPLIT;  // 87
static constexpr int MTILES = N_NODES / BM;              // 64
static constexpr int NTHR = 128;                         // 4 warps

__device__ float         g_aggr[N_NODES * DD];
__device__ __nv_bfloat16 g_Ehi[(size_t)N_ENT * DD];
__device__ __nv_bfloat16 g_Elo[(size_t)N_ENT * DD];

// ---- smem map (bytes) ------------------------------------------------------
static constexpr int SM_AHI = 0;          // 16384  A_hi [64m,128k]
static constexpr int SM_ALO = 16384;      // 16384
static constexpr int SM_EB  = 32768;      // 2 bufs x 32768
static constexpr int EB_HI  = 0;          // 16384  E [64v,128d]
static constexpr int EB_LO  = 16384;      // 16384
static constexpr int EB_STRIDE = 32768;
static constexpr int SM_SHI = 98304;      // 8192   S' [64m,64v]
static constexpr int SM_SLO = 106496;     // 8192
static constexpr int SMEM_BYTES = 114688; // x2 CTAs = 229376 <= 228KB/SM

// ---------------------------------------------------------------------------
__device__ __forceinline__ uint32_t s2u(const void* p) {
    uint32_t a;
    asm("{ .reg .u64 t; cvta.to.shared.u64 t, %1; cvt.u32.u64 %0, t; }" : "=r"(a) : "l"(p));
    return a;
}
// swizzled offsets: 16B chunks XOR'ed by (row & 7)
__device__ __forceinline__ uint32_t off128(int r, int c) {   // 128 bf16/row
    return (uint32_t)(r * 256) + ((((c >> 3) ^ (r & 7)) << 4) | ((c & 7) * 2));
}
__device__ __forceinline__ uint32_t off64(int r, int c) {    // 64 bf16/row
    return (uint32_t)(r * 128) + ((((c >> 3) ^ (r & 7)) << 4) | ((c & 7) * 2));
}
__device__ __forceinline__ void cpa16(uint32_t dst, const void* src, int srcsize) {
    asm volatile("cp.async.cg.shared.global [%0], [%1], 16, %2;"
                 :: "r"(dst), "l"(src), "r"(srcsize) : "memory");
}
__device__ __forceinline__ void cpa_commit() { asm volatile("cp.async.commit_group;" ::: "memory"); }
__device__ __forceinline__ void cpa_wait0()  { asm volatile("cp.async.wait_group 0;"  ::: "memory"); }

__device__ __forceinline__ void ldm4(uint32_t& r0, uint32_t& r1, uint32_t& r2, uint32_t& r3, uint32_t a) {
    asm volatile("ldmatrix.sync.aligned.m8n8.x4.shared.b16 {%0,%1,%2,%3}, [%4];"
                 : "=r"(r0), "=r"(r1), "=r"(r2), "=r"(r3) : "r"(a));
}
__device__ __forceinline__ void ldm4t(uint32_t& r0, uint32_t& r1, uint32_t& r2, uint32_t& r3, uint32_t a) {
    asm volatile("ldmatrix.sync.aligned.m8n8.x4.trans.shared.b16 {%0,%1,%2,%3}, [%4];"
                 : "=r"(r0), "=r"(r1), "=r"(r2), "=r"(r3) : "r"(a));
}
__device__ __forceinline__ void mma16816(float* d, const uint32_t* a, const uint32_t* b) {
    asm volatile("mma.sync.aligned.m16n8k16.row.col.f32.bf16.bf16.f32 "
                 "{%0,%1,%2,%3}, {%4,%5,%6,%7}, {%8,%9}, {%0,%1,%2,%3};"
                 : "+f"(d[0]), "+f"(d[1]), "+f"(d[2]), "+f"(d[3])
                 : "r"(a[0]), "r"(a[1]), "r"(a[2]), "r"(a[3]), "r"(b[0]), "r"(b[1]));
}
__device__ __forceinline__ void red_add_v2(float* p, float a, float b) {
    asm volatile("red.global.add.v2.f32 [%0], {%1, %2};" :: "l"(p), "f"(a), "f"(b) : "memory");
}
__device__ __forceinline__ void red_add_v4(float* p, float a, float b, float c, float d) {
    asm volatile("red.global.add.v4.f32 [%0], {%1, %2, %3, %4};"
                 :: "l"(p), "f"(a), "f"(b), "f"(c), "f"(d) : "memory");
}
// hp = {hi16: bf16(b), lo16: bf16(a)}, lp likewise for residuals
__device__ __forceinline__ void split2(float a, float b, uint32_t& hp, uint32_t& lp) {
    asm("cvt.rn.bf16x2.f32 %0, %1, %2;" : "=r"(hp) : "f"(b), "f"(a));
    float ha = __uint_as_float(hp << 16);
    float hb = __uint_as_float(hp & 0xFFFF0000u);
    asm("cvt.rn.bf16x2.f32 %0, %1, %2;" : "=r"(lp) : "f"(b - hb), "f"(a - ha));
}
#define BARPAIR(id) asm volatile("bar.sync %0, 64;" :: "r"(id) : "memory")

// ---------------------------------------------------------------------------
__global__ void init_kernel(const float* __restrict__ x, float* __restrict__ out) {
    int i = blockIdx.x * blockDim.x + threadIdx.x;
    if (i < N_NODES * DD) { g_aggr[i] = 0.1f * x[i]; out[i] = 0.0f; }
}

__global__ void scatter_kernel(const float* __restrict__ x, const int* __restrict__ eidx,
                               const int* __restrict__ rid, const int* __restrict__ neg,
                               const float* __restrict__ rel) {
    int gw = (blockIdx.x * blockDim.x + threadIdx.x) >> 5;
    int lane = threadIdx.x & 31;
    if (gw >= N_EDGES) return;
    int src = eidx[gw], dst = eidx[N_EDGES + gw], r = rid[gw];
    float coef = 1.0f - 2.0f * (float)neg[gw];
    float4 xv = ((const float4*)(x + (size_t)src * DD))[lane];
    float4 rv = ((const float4*)(rel + (size_t)r * DD))[lane];
    red_add_v4(g_aggr + (size_t)dst * DD + lane * 4,
               (xv.x + rv.x) * coef, (xv.y + rv.y) * coef,
               (xv.z + rv.z) * coef, (xv.w + rv.w) * coef);
}

__global__ void prep_kernel(const float* __restrict__ eemb) {
    int i = blockIdx.x * blockDim.x + threadIdx.x;    // over N_ENT*64 float2
    if (i >= N_ENT * (DD / 2)) return;
    float2 v = ((const float2*)eemb)[i];
    uint32_t hp, lp; split2(v.x, v.y, hp, lp);
    ((uint32_t*)g_Ehi)[i] = hp;
    ((uint32_t*)g_Elo)[i] = lp;
}

// ---------------------------------------------------------------------------
__global__ void __launch_bounds__(NTHR, 2)
gemm_fused(const float* __restrict__ scal, const float* __restrict__ bias,
           float* __restrict__ out) {
    extern __shared__ char smem[];
    const uint32_t sb = s2u(smem);
    const int tid = threadIdx.x, wid = tid >> 5, lane = tid & 31;
    const int mt = blockIdx.x & (MTILES - 1), sp = blockIdx.x / MTILES;
    const int m0 = mt * BM;
    const int t0 = sp * TPS, t1 = min(NVT, t0 + TPS);
    if (t0 >= t1) return;

    const int wm = (wid >> 1) * 32;        // warp m-offset: 2 warp-rows x 32
    const int wsel = wid & 1;              // GEMM1: v half; GEMM2: d half
    const int barid = 1 + (wid >> 1);      // pair barrier id (warps wm/wsel0,1)

    // ---- A tile: g_aggr f32 -> hi/lo bf16, swizzled ----
    for (int i = tid; i < BM * (DD / 4); i += NTHR) {
        int m = i >> 5, k = (i & 31) * 4;
        float4 a = *(const float4*)(g_aggr + (size_t)(m0 + m) * DD + k);
        uint32_t h01, l01, h23, l23;
        split2(a.x, a.y, h01, l01);
        split2(a.z, a.w, h23, l23);
        uint32_t o0 = off128(m, k), o1 = off128(m, k + 2);
        *(uint32_t*)(smem + SM_AHI + o0) = h01; *(uint32_t*)(smem + SM_AHI + o1) = h23;
        *(uint32_t*)(smem + SM_ALO + o0) = l01; *(uint32_t*)(smem + SM_ALO + o1) = l23;
    }

    auto load_tiles = [&](int t, int b) {
        const int v0 = t * BV;
        const uint32_t eb = sb + SM_EB + b * EB_STRIDE;
        for (int i = tid; i < 1024; i += NTHR) {    // E [64v,128d] hi/lo, 16B chunks
            int v = i >> 4, dg = (i & 15) * 8;
            int gv = v0 + v;
            uint32_t o = off128(v, dg);
            int sz = (gv < N_ENT) ? 16 : 0;
            const void* pH = sz ? (const void*)(g_Ehi + (size_t)gv * DD + dg) : (const void*)g_Ehi;
            const void* pL = sz ? (const void*)(g_Elo + (size_t)gv * DD + dg) : (const void*)g_Elo;
            cpa16(eb + EB_HI + o, pH, sz);
            cpa16(eb + EB_LO + o, pL, sz);
        }
    };

    float accO[2][8][4];
    #pragma unroll
    for (int mi = 0; mi < 2; mi++)
        #pragma unroll
        for (int nt = 0; nt < 8; nt++)
            #pragma unroll
            for (int q = 0; q < 4; q++) accO[mi][nt][q] = 0.0f;

    load_tiles(t0, 0);
    cpa_commit();

    // per-lane ldmatrix row/col pieces (constant across loop)
    const int lr16 = lane & 15;            // row within 16
    const int lc8  = (lane >> 4) << 3;     // +8 col for upper half-warp
    const int lrB  = (lane & 7) | ((lane & 16) >> 1);  // B non-trans row
    const int lcB  = lane & 8;                          // B non-trans col sel
    const int ce   = (lane & 3) * 2;       // epilogue col pair base

    for (int t = t0; t < t1; ++t) {
        const int buf = (t - t0) & 1;
        const uint32_t eb = sb + SM_EB + buf * EB_STRIDE;

        // prefetch scale/bias for this tile's columns (L2-resident)
        float2 scv[4], biv[4];
        {
            const int v0t = t * BV;
            #pragma unroll
            for (int nt = 0; nt < 4; nt++) {
                int gc = v0t + wsel * 32 + nt * 8 + ce;
                if (gc + 1 < N_ENT) {
                    scv[nt] = __ldg((const float2*)(scal + gc));
                    biv[nt] = __ldg((const float2*)(bias + gc));
                } else {
                    scv[nt].x = (gc < N_ENT) ? __ldg(scal + gc) : 0.f;
                    scv[nt].y = 0.f;
                    biv[nt].x = (gc < N_ENT) ? __ldg(bias + gc) : 0.f;
                    biv[nt].y = 0.f;
                }
            }
        }

        cpa_wait0();           // tile t landed (this thread's copies)
        __syncthreads();       // visible to all; all warps done with buf^1 + S'
        if (t + 1 < t1) { load_tiles(t + 1, buf ^ 1); cpa_commit(); }

        // ---------------- GEMM1: S[64m x 64v] = A . E^T (3 split passes) -----
        float accS[2][4][4];
        #pragma unroll
        for (int mi = 0; mi < 2; mi++)
            #pragma unroll
            for (int nt = 0; nt < 4; nt++)
                #pragma unroll
                for (int q = 0; q < 4; q++) accS[mi][nt][q] = 0.0f;

        #pragma unroll
        for (int ks = 0; ks < 8; ks++) {
            const int k0 = ks * 16;
            uint32_t aH[2][4], aL[2][4];
            #pragma unroll
            for (int mi = 0; mi < 2; mi++) {
                uint32_t o = off128(wm + mi * 16 + lr16, k0 + lc8);
                ldm4(aH[mi][0], aH[mi][1], aH[mi][2], aH[mi][3], sb + SM_AHI + o);
                ldm4(aL[mi][0], aL[mi][1], aL[mi][2], aL[mi][3], sb + SM_ALO + o);
            }
            uint32_t bH[4][2], bL[4][2];
            #pragma unroll
            for (int ng = 0; ng < 2; ng++) {
                uint32_t o = off128(wsel * 32 + ng * 16 + lrB, k0 + lcB);
                uint32_t r0, r1, r2, r3;
                ldm4(r0, r1, r2, r3, eb + EB_HI + o);
                bH[ng * 2][0] = r0; bH[ng * 2][1] = r1;
                bH[ng * 2 + 1][0] = r2; bH[ng * 2 + 1][1] = r3;
                ldm4(r0, r1, r2, r3, eb + EB_LO + o);
                bL[ng * 2][0] = r0; bL[ng * 2][1] = r1;
                bL[ng * 2 + 1][0] = r2; bL[ng * 2 + 1][1] = r3;
            }
            #pragma unroll
            for (int mi = 0; mi < 2; mi++)
                #pragma unroll
                for (int nt = 0; nt < 4; nt++) {
                    mma16816(accS[mi][nt], aH[mi], bH[nt]);
                    mma16816(accS[mi][nt], aH[mi], bL[nt]);
                    mma16816(accS[mi][nt], aL[mi], bH[nt]);
                }
        }

        // ---------------- epilogue: relu(scale*s+bias), split -> S' smem -----
        {
            #pragma unroll
            for (int mi = 0; mi < 2; mi++) {
                const int r0 = wm + mi * 16 + (lane >> 2);
                #pragma unroll
                for (int nt = 0; nt < 4; nt++) {
                    const int c = wsel * 32 + nt * 8 + ce;
                    float s0 = scv[nt].x, s1 = scv[nt].y, b0 = biv[nt].x, b1 = biv[nt].y;
                    float v00 = fmaxf(fmaf(accS[mi][nt][0], s0, b0), 0.f);
                    float v01 = fmaxf(fmaf(accS[mi][nt][1], s1, b1), 0.f);
                    float v10 = fmaxf(fmaf(accS[mi][nt][2], s0, b0), 0.f);
                    float v11 = fmaxf(fmaf(accS[mi][nt][3], s1, b1), 0.f);
                    uint32_t hp, lp;
                    split2(v00, v01, hp, lp);
                    uint32_t o = off64(r0, c);
                    *(uint32_t*)(smem + SM_SHI + o) = hp;
                    *(uint32_t*)(smem + SM_SLO + o) = lp;
                    split2(v10, v11, hp, lp);
                    o = off64(r0 + 8, c);
                    *(uint32_t*)(smem + SM_SHI + o) = hp;
                    *(uint32_t*)(smem + SM_SLO + o) = lp;
                }
            }
        }
        BARPAIR(barid);   // only the (wm) pair shares S' rows

        // ---------------- GEMM2: O[64m x 128d] += S' . E (3 split passes) ----
        #pragma unroll
        for (int ks = 0; ks < 4; ks++) {
            const int k0 = ks * 16;
            uint32_t aH[2][4], aL[2][4];
            #pragma unroll
            for (int mi = 0; mi < 2; mi++) {
                uint32_t o = off64(wm + mi * 16 + lr16, k0 + lc8);
                ldm4(aH[mi][0], aH[mi][1], aH[mi][2], aH[mi][3], sb + SM_SHI + o);
                ldm4(aL[mi][0], aL[mi][1], aL[mi][2], aL[mi][3], sb + SM_SLO + o);
            }
            #pragma unroll
            for (int half = 0; half < 2; half++) {      // nt 0-3, then 4-7
                uint32_t bH[4][2], bL[4][2];
                #pragma unroll
                for (int ng = 0; ng < 2; ng++) {
                    uint32_t o = off128(k0 + lr16, wsel * 64 + half * 32 + ng * 16 + lc8);
                    uint32_t r0, r1, r2, r3;
                    ldm4t(r0, r1, r2, r3, eb + EB_HI + o);
                    bH[ng * 2][0] = r0; bH[ng * 2][1] = r1;
                    bH[ng * 2 + 1][0] = r2; bH[ng * 2 + 1][1] = r3;
                    ldm4t(r0, r1, r2, r3, eb + EB_LO + o);
                    bL[ng * 2][0] = r0; bL[ng * 2][1] = r1;
                    bL[ng * 2 + 1][0] = r2; bL[ng * 2 + 1][1] = r3;
                }
                #pragma unroll
                for (int mi = 0; mi < 2; mi++)
                    #pragma unroll
                    for (int ng = 0; ng < 4; ng++) {
                        float* d = accO[mi][half * 4 + ng];
                        mma16816(d, aH[mi], bH[ng]);
                        mma16816(d, aH[mi], bL[ng]);
                        mma16816(d, aL[mi], bH[ng]);
                    }
            }
        }
    }

    // ---- flush O to out (+= across splits) ----
    #pragma unroll
    for (int mi = 0; mi < 2; mi++) {
        const int r0 = m0 + wm + mi * 16 + (lane >> 2);
        #pragma unroll
        for (int nt = 0; nt < 8; nt++) {
            const int c = wsel * 64 + nt * 8 + ce;
            red_add_v2(out + (size_t)r0 * DD + c,       accO[mi][nt][0], accO[mi][nt][1]);
            red_add_v2(out + (size_t)(r0 + 8) * DD + c, accO[mi][nt][2], accO[mi][nt][3]);
        }
    }
}

// ---------------------------------------------------------------------------
extern "C" void kernel_launch(void* const* d_in, const int* in_sizes, int n_in,
                              void* d_out, int out_size) {
    const float* x     = (const float*)d_in[0];
    const int*   eidx  = (const int*)  d_in[1];
    const int*   rid   = (const int*)  d_in[2];
    const int*   neg   = (const int*)  d_in[3];
    const float* rel   = (const float*)d_in[4];
    const float* eemb  = (const float*)d_in[5];
    const float* scale = (const float*)d_in[6];
    const float* bias  = (const float*)d_in[7];
    float* out = (float*)d_out;

    cudaFuncSetAttribute(gemm_fused, cudaFuncAttributeMaxDynamicSharedMemorySize, SMEM_BYTES);

    prep_kernel<<<(N_ENT * (DD / 2) + 255) / 256, 256>>>(eemb);
    init_kernel<<<(N_NODES * DD + 255) / 256, 256>>>(x, out);
    scatter_kernel<<<N_EDGES * 32 / 256, 256>>>(x, eidx, rid, neg, rel);
    gemm_fused<<<MTILES * NSPLIT, NTHR, SMEM_BYTES>>>(scale, bias, out);
}

// round 7
// speedup vs baseline: 4.9258x; 1.0409x over previous
#include <cuda_runtime.h>
#include <cuda_bf16.h>
#include <cstdint>

// ---------------------------------------------------------------------------
// LMPNN round 7: bf16x3 fused double-GEMM, register-resident S' handoff.
// GEMM1 warp tile 16m x 64v; its C fragments are relu'd/scaled and repacked
// in registers directly into GEMM2 A fragments (C->A layout identity), so
// S' never touches smem and the mid-tile barrier disappears.
// ---------------------------------------------------------------------------

#define DD 128
static constexpr int N_NODES = 4096;
static constexpr int N_EDGES = 262144;
static constexpr int N_ENT   = 50000;

static constexpr int BM = 64;
static constexpr int BV = 64;
static constexpr int NVT = (N_ENT + BV - 1) / BV;        // 782
static constexpr int NSPLIT = 9;
static constexpr int TPS = (NVT + NSPLIT - 1) / NSPLIT;  // 87
static constexpr int MTILES = N_NODES / BM;              // 64
static constexpr int NTHR = 128;                         // 4 warps

__device__ float         g_aggr[N_NODES * DD];
__device__ __nv_bfloat16 g_Ehi[(size_t)N_ENT * DD];
__device__ __nv_bfloat16 g_Elo[(size_t)N_ENT * DD];

// ---- smem map (bytes) ------------------------------------------------------
static constexpr int SM_AHI = 0;          // 16384  A_hi [64m,128k]
static constexpr int SM_ALO = 16384;      // 16384
static constexpr int SM_EB  = 32768;      // 2 bufs x 33280
static constexpr int EB_HI  = 0;          // 16384  E [64v,128d]
static constexpr int EB_LO  = 16384;      // 16384
static constexpr int EB_SCB = 32768;      // 512 (64 scale f32 + 64 bias f32)
static constexpr int EB_STRIDE = 33280;
static constexpr int SMEM_BYTES = 32768 + 2 * EB_STRIDE;  // 99328; x2 CTAs ok

// ---------------------------------------------------------------------------
__device__ __forceinline__ uint32_t s2u(const void* p) {
    uint32_t a;
    asm("{ .reg .u64 t; cvta.to.shared.u64 t, %1; cvt.u32.u64 %0, t; }" : "=r"(a) : "l"(p));
    return a;
}
// swizzled offsets: 16B chunks XOR'ed by (row & 7)
__device__ __forceinline__ uint32_t off128(int r, int c) {   // 128 bf16/row
    return (uint32_t)(r * 256) + ((((c >> 3) ^ (r & 7)) << 4) | ((c & 7) * 2));
}
__device__ __forceinline__ void cpa16(uint32_t dst, const void* src, int srcsize) {
    asm volatile("cp.async.cg.shared.global [%0], [%1], 16, %2;"
                 :: "r"(dst), "l"(src), "r"(srcsize) : "memory");
}
__device__ __forceinline__ void cpa_commit() { asm volatile("cp.async.commit_group;" ::: "memory"); }
__device__ __forceinline__ void cpa_wait0()  { asm volatile("cp.async.wait_group 0;"  ::: "memory"); }

__device__ __forceinline__ void ldm4(uint32_t& r0, uint32_t& r1, uint32_t& r2, uint32_t& r3, uint32_t a) {
    asm volatile("ldmatrix.sync.aligned.m8n8.x4.shared.b16 {%0,%1,%2,%3}, [%4];"
                 : "=r"(r0), "=r"(r1), "=r"(r2), "=r"(r3) : "r"(a));
}
__device__ __forceinline__ void ldm4t(uint32_t& r0, uint32_t& r1, uint32_t& r2, uint32_t& r3, uint32_t a) {
    asm volatile("ldmatrix.sync.aligned.m8n8.x4.trans.shared.b16 {%0,%1,%2,%3}, [%4];"
                 : "=r"(r0), "=r"(r1), "=r"(r2), "=r"(r3) : "r"(a));
}
__device__ __forceinline__ void mma16816(float* d, const uint32_t* a, const uint32_t* b) {
    asm volatile("mma.sync.aligned.m16n8k16.row.col.f32.bf16.bf16.f32 "
                 "{%0,%1,%2,%3}, {%4,%5,%6,%7}, {%8,%9}, {%0,%1,%2,%3};"
                 : "+f"(d[0]), "+f"(d[1]), "+f"(d[2]), "+f"(d[3])
                 : "r"(a[0]), "r"(a[1]), "r"(a[2]), "r"(a[3]), "r"(b[0]), "r"(b[1]));
}
__device__ __forceinline__ void red_add_v2(float* p, float a, float b) {
    asm volatile("red.global.add.v2.f32 [%0], {%1, %2};" :: "l"(p), "f"(a), "f"(b) : "memory");
}
__device__ __forceinline__ void red_add_v4(float* p, float a, float b, float c, float d) {
    asm volatile("red.global.add.v4.f32 [%0], {%1, %2, %3, %4};"
                 :: "l"(p), "f"(a), "f"(b), "f"(c), "f"(d) : "memory");
}
// hp = bf16x2(a lo-half, b hi-half); lp = residuals
__device__ __forceinline__ void split2(float a, float b, uint32_t& hp, uint32_t& lp) {
    asm("cvt.rn.bf16x2.f32 %0, %1, %2;" : "=r"(hp) : "f"(b), "f"(a));
    float ha = __uint_as_float(hp << 16);
    float hb = __uint_as_float(hp & 0xFFFF0000u);
    asm("cvt.rn.bf16x2.f32 %0, %1, %2;" : "=r"(lp) : "f"(b - hb), "f"(a - ha));
}

// ---------------------------------------------------------------------------
__global__ void init_kernel(const float* __restrict__ x, float* __restrict__ out) {
    int i = blockIdx.x * blockDim.x + threadIdx.x;
    if (i < N_NODES * DD) { g_aggr[i] = 0.1f * x[i]; out[i] = 0.0f; }
}

__global__ void scatter_kernel(const float* __restrict__ x, const int* __restrict__ eidx,
                               const int* __restrict__ rid, const int* __restrict__ neg,
                               const float* __restrict__ rel) {
    int gw = (blockIdx.x * blockDim.x + threadIdx.x) >> 5;
    int lane = threadIdx.x & 31;
    if (gw >= N_EDGES) return;
    int src = eidx[gw], dst = eidx[N_EDGES + gw], r = rid[gw];
    float coef = 1.0f - 2.0f * (float)neg[gw];
    float4 xv = ((const float4*)(x + (size_t)src * DD))[lane];
    float4 rv = ((const float4*)(rel + (size_t)r * DD))[lane];
    red_add_v4(g_aggr + (size_t)dst * DD + lane * 4,
               (xv.x + rv.x) * coef, (xv.y + rv.y) * coef,
               (xv.z + rv.z) * coef, (xv.w + rv.w) * coef);
}

__global__ void prep_kernel(const float* __restrict__ eemb) {
    int i = blockIdx.x * blockDim.x + threadIdx.x;    // over N_ENT*64 float2
    if (i >= N_ENT * (DD / 2)) return;
    float2 v = ((const float2*)eemb)[i];
    uint32_t hp, lp; split2(v.x, v.y, hp, lp);
    ((uint32_t*)g_Ehi)[i] = hp;
    ((uint32_t*)g_Elo)[i] = lp;
}

// ---------------------------------------------------------------------------
__global__ void __launch_bounds__(NTHR, 2)
gemm_fused(const float* __restrict__ scal, const float* __restrict__ bias,
           float* __restrict__ out) {
    extern __shared__ char smem[];
    const uint32_t sb = s2u(smem);
    const int tid = threadIdx.x, wid = tid >> 5, lane = tid & 31;
    const int mt = blockIdx.x & (MTILES - 1), sp = blockIdx.x / MTILES;
    const int m0 = mt * BM;
    const int t0 = sp * TPS, t1 = min(NVT, t0 + TPS);
    if (t0 >= t1) return;

    const int wm = wid * 16;               // warp owns rows [wm, wm+16)

    // ---- A tile: g_aggr f32 -> hi/lo bf16, swizzled ----
    for (int i = tid; i < BM * (DD / 4); i += NTHR) {
        int m = i >> 5, k = (i & 31) * 4;
        float4 a = *(const float4*)(g_aggr + (size_t)(m0 + m) * DD + k);
        uint32_t h01, l01, h23, l23;
        split2(a.x, a.y, h01, l01);
        split2(a.z, a.w, h23, l23);
        uint32_t o0 = off128(m, k), o1 = off128(m, k + 2);
        *(uint32_t*)(smem + SM_AHI + o0) = h01; *(uint32_t*)(smem + SM_AHI + o1) = h23;
        *(uint32_t*)(smem + SM_ALO + o0) = l01; *(uint32_t*)(smem + SM_ALO + o1) = l23;
    }

    auto load_tiles = [&](int t, int b) {
        const int v0 = t * BV;
        const uint32_t eb = sb + SM_EB + b * EB_STRIDE;
        for (int i = tid; i < 1024; i += NTHR) {    // E [64v,128d] hi/lo, 16B chunks
            int v = i >> 4, dg = (i & 15) * 8;
            int gv = v0 + v;
            uint32_t o = off128(v, dg);
            int sz = (gv < N_ENT) ? 16 : 0;
            const void* pH = sz ? (const void*)(g_Ehi + (size_t)gv * DD + dg) : (const void*)g_Ehi;
            const void* pL = sz ? (const void*)(g_Elo + (size_t)gv * DD + dg) : (const void*)g_Elo;
            cpa16(eb + EB_HI + o, pH, sz);
            cpa16(eb + EB_LO + o, pL, sz);
        }
        if (tid < 32) {                              // 64 scale + 64 bias f32
            int half = tid >> 4, g = tid & 15;
            int gv = v0 + g * 4;
            int rem = N_ENT - gv;
            int sz = rem >= 4 ? 16 : (rem > 0 ? rem * 4 : 0);
            const float* src = half ? bias : scal;
            const void* p = sz ? (const void*)(src + gv) : (const void*)src;
            cpa16(eb + EB_SCB + half * 256 + g * 16, p, sz);
        }
    };

    float accO[16][4];                      // 16m x 128d per warp
    #pragma unroll
    for (int nt = 0; nt < 16; nt++)
        #pragma unroll
        for (int q = 0; q < 4; q++) accO[nt][q] = 0.0f;

    load_tiles(t0, 0);
    cpa_commit();

    // per-lane ldmatrix pieces (constant across loop)
    const int lr16 = lane & 15;            // row within 16
    const int lc8  = (lane >> 4) << 3;     // +8 col for upper half-warp
    const int lrB  = (lane & 7) | ((lane & 16) >> 1);  // B non-trans row
    const int lcB  = lane & 8;                          // B non-trans col sel
    const int ce   = (lane & 3) * 2;       // C/epilogue col pair base

    for (int t = t0; t < t1; ++t) {
        const int buf = (t - t0) & 1;
        const uint32_t eb = sb + SM_EB + buf * EB_STRIDE;

        cpa_wait0();           // tile t landed (this thread's copies)
        __syncthreads();       // visible to all; all warps done with buf^1
        if (t + 1 < t1) { load_tiles(t + 1, buf ^ 1); cpa_commit(); }

        // ---------------- GEMM1: S[16m x 64v] per warp (3 split passes) ------
        float accS[8][4];
        #pragma unroll
        for (int nt = 0; nt < 8; nt++)
            #pragma unroll
            for (int q = 0; q < 4; q++) accS[nt][q] = 0.0f;

        #pragma unroll
        for (int ks = 0; ks < 8; ks++) {
            const int k0 = ks * 16;
            uint32_t aH[4], aL[4];
            {
                uint32_t o = off128(wm + lr16, k0 + lc8);
                ldm4(aH[0], aH[1], aH[2], aH[3], sb + SM_AHI + o);
                ldm4(aL[0], aL[1], aL[2], aL[3], sb + SM_ALO + o);
            }
            uint32_t bH[8][2], bL[8][2];
            #pragma unroll
            for (int ng = 0; ng < 4; ng++) {
                uint32_t o = off128(ng * 16 + lrB, k0 + lcB);
                uint32_t r0, r1, r2, r3;
                ldm4(r0, r1, r2, r3, eb + EB_HI + o);
                bH[ng * 2][0] = r0; bH[ng * 2][1] = r1;
                bH[ng * 2 + 1][0] = r2; bH[ng * 2 + 1][1] = r3;
                ldm4(r0, r1, r2, r3, eb + EB_LO + o);
                bL[ng * 2][0] = r0; bL[ng * 2][1] = r1;
                bL[ng * 2 + 1][0] = r2; bL[ng * 2 + 1][1] = r3;
            }
            #pragma unroll
            for (int nt = 0; nt < 8; nt++) {
                mma16816(accS[nt], aH, bH[nt]);
                mma16816(accS[nt], aH, bL[nt]);
                mma16816(accS[nt], aL, bH[nt]);
            }
        }

        // ------- epilogue in registers: relu(scale*s+bias) -> GEMM2 A frags --
        // C->A identity: a0=(r,k0k1), a1=(r+8,k0k1), a2=(r,k8k9), a3=(r+8,k8k9)
        uint32_t aSh[4][4], aSl[4][4];
        {
            const float* scb = (const float*)(smem + SM_EB + buf * EB_STRIDE + EB_SCB);
            #pragma unroll
            for (int nt = 0; nt < 8; nt++) {
                const int c = nt * 8 + ce;
                float2 scv = *(const float2*)(scb + c);
                float2 biv = *(const float2*)(scb + 64 + c);
                float v00 = fmaxf(fmaf(accS[nt][0], scv.x, biv.x), 0.f);
                float v01 = fmaxf(fmaf(accS[nt][1], scv.y, biv.y), 0.f);
                float v10 = fmaxf(fmaf(accS[nt][2], scv.x, biv.x), 0.f);
                float v11 = fmaxf(fmaf(accS[nt][3], scv.y, biv.y), 0.f);
                const int g = nt >> 1, sub = (nt & 1) * 2;
                split2(v00, v01, aSh[g][sub],     aSl[g][sub]);
                split2(v10, v11, aSh[g][sub + 1], aSl[g][sub + 1]);
            }
        }

        // ---------------- GEMM2: O[16m x 128d] += S' . E (3 split passes) ----
        #pragma unroll
        for (int g = 0; g < 4; g++) {          // k16 groups over v
            const int k0 = g * 16;
            #pragma unroll
            for (int half = 0; half < 2; half++) {
                uint32_t bH[8][2], bL[8][2];
                #pragma unroll
                for (int ng = 0; ng < 4; ng++) {
                    uint32_t o = off128(k0 + lr16, half * 64 + ng * 16 + lc8);
                    uint32_t r0, r1, r2, r3;
                    ldm4t(r0, r1, r2, r3, eb + EB_HI + o);
                    bH[ng * 2][0] = r0; bH[ng * 2][1] = r1;
                    bH[ng * 2 + 1][0] = r2; bH[ng * 2 + 1][1] = r3;
                    ldm4t(r0, r1, r2, r3, eb + EB_LO + o);
                    bL[ng * 2][0] = r0; bL[ng * 2][1] = r1;
                    bL[ng * 2 + 1][0] = r2; bL[ng * 2 + 1][1] = r3;
                }
                #pragma unroll
                for (int ng = 0; ng < 8; ng++) {
                    float* d = accO[half * 8 + ng];
                    mma16816(d, aSh[g], bH[ng]);
                    mma16816(d, aSh[g], bL[ng]);
                    mma16816(d, aSl[g], bH[ng]);
                }
            }
        }
    }

    // ---- flush O to out (+= across splits) ----
    {
        const int r0 = m0 + wm + (lane >> 2);
        #pragma unroll
        for (int nt = 0; nt < 16; nt++) {
            const int c = nt * 8 + ce;
            red_add_v2(out + (size_t)r0 * DD + c,       accO[nt][0], accO[nt][1]);
            red_add_v2(out + (size_t)(r0 + 8) * DD + c, accO[nt][2], accO[nt][3]);
        }
    }
}

// ---------------------------------------------------------------------------
extern "C" void kernel_launch(void* const* d_in, const int* in_sizes, int n_in,
                              void* d_out, int out_size) {
    const float* x     = (const float*)d_in[0];
    const int*   eidx  = (const int*)  d_in[1];
    const int*   rid   = (const int*)  d_in[2];
    const int*   neg   = (const int*)  d_in[3];
    const float* rel   = (const float*)d_in[4];
    const float* eemb  = (const float*)d_in[5];
    const float* scale = (const float*)d_in[6];
    const float* bias  = (const float*)d_in[7];
    float* out = (float*)d_out;

    cudaFuncSetAttribute(gemm_fused, cudaFuncAttributeMaxDynamicSharedMemorySize, SMEM_BYTES);

    prep_kernel<<<(N_ENT * (DD / 2) + 255) / 256, 256>>>(eemb);
    init_kernel<<<(N_NODES * DD + 255) / 256, 256>>>(x, out);
    scatter_kernel<<<N_EDGES * 32 / 256, 256>>>(x, eidx, rid, neg, rel);
    gemm_fused<<<MTILES * NSPLIT, NTHR, SMEM_BYTES>>>(scale, bias, out);
}

// round 8
// speedup vs baseline: 4.9694x; 1.0088x over previous
#include <cuda_runtime.h>
#include <cuda_bf16.h>
#include <cstdint>

// ---------------------------------------------------------------------------
// LMPNN round 8: bf16x3 fused double-GEMM, register-resident S' handoff,
// A fragments hoisted to registers ONCE (invariant across entity tiles):
// GEMM1 does zero A-LDSM per tile and starts each k-step MMA-ready.
// ---------------------------------------------------------------------------

#define DD 128
static constexpr int N_NODES = 4096;
static constexpr int N_EDGES = 262144;
static constexpr int N_ENT   = 50000;

static constexpr int BM = 64;
static constexpr int BV = 64;
static constexpr int NVT = (N_ENT + BV - 1) / BV;        // 782
static constexpr int NSPLIT = 9;
static constexpr int TPS = (NVT + NSPLIT - 1) / NSPLIT;  // 87
static constexpr int MTILES = N_NODES / BM;              // 64
static constexpr int NTHR = 128;                         // 4 warps

__device__ float         g_aggr[N_NODES * DD];
__device__ __nv_bfloat16 g_Ehi[(size_t)N_ENT * DD];
__device__ __nv_bfloat16 g_Elo[(size_t)N_ENT * DD];

// ---- smem map (bytes) ------------------------------------------------------
static constexpr int SM_AHI = 0;          // 16384  A_hi [64m,128k] (read once)
static constexpr int SM_ALO = 16384;      // 16384
static constexpr int SM_EB  = 32768;      // 2 bufs x 33280
static constexpr int EB_HI  = 0;          // 16384  E [64v,128d]
static constexpr int EB_LO  = 16384;      // 16384
static constexpr int EB_SCB = 32768;      // 512 (64 scale f32 + 64 bias f32)
static constexpr int EB_STRIDE = 33280;
static constexpr int SMEM_BYTES = 32768 + 2 * EB_STRIDE;  // 99328; x2 CTAs ok

// ---------------------------------------------------------------------------
__device__ __forceinline__ uint32_t s2u(const void* p) {
    uint32_t a;
    asm("{ .reg .u64 t; cvta.to.shared.u64 t, %1; cvt.u32.u64 %0, t; }" : "=r"(a) : "l"(p));
    return a;
}
// swizzled offsets: 16B chunks XOR'ed by (row & 7)
__device__ __forceinline__ uint32_t off128(int r, int c) {   // 128 bf16/row
    return (uint32_t)(r * 256) + ((((c >> 3) ^ (r & 7)) << 4) | ((c & 7) * 2));
}
__device__ __forceinline__ void cpa16(uint32_t dst, const void* src, int srcsize) {
    asm volatile("cp.async.cg.shared.global [%0], [%1], 16, %2;"
                 :: "r"(dst), "l"(src), "r"(srcsize) : "memory");
}
__device__ __forceinline__ void cpa_commit() { asm volatile("cp.async.commit_group;" ::: "memory"); }
__device__ __forceinline__ void cpa_wait0()  { asm volatile("cp.async.wait_group 0;"  ::: "memory"); }

__device__ __forceinline__ void ldm4(uint32_t& r0, uint32_t& r1, uint32_t& r2, uint32_t& r3, uint32_t a) {
    asm volatile("ldmatrix.sync.aligned.m8n8.x4.shared.b16 {%0,%1,%2,%3}, [%4];"
                 : "=r"(r0), "=r"(r1), "=r"(r2), "=r"(r3) : "r"(a));
}
__device__ __forceinline__ void ldm4t(uint32_t& r0, uint32_t& r1, uint32_t& r2, uint32_t& r3, uint32_t a) {
    asm volatile("ldmatrix.sync.aligned.m8n8.x4.trans.shared.b16 {%0,%1,%2,%3}, [%4];"
                 : "=r"(r0), "=r"(r1), "=r"(r2), "=r"(r3) : "r"(a));
}
__device__ __forceinline__ void mma16816(float* d, const uint32_t* a, const uint32_t* b) {
    asm volatile("mma.sync.aligned.m16n8k16.row.col.f32.bf16.bf16.f32 "
                 "{%0,%1,%2,%3}, {%4,%5,%6,%7}, {%8,%9}, {%0,%1,%2,%3};"
                 : "+f"(d[0]), "+f"(d[1]), "+f"(d[2]), "+f"(d[3])
                 : "r"(a[0]), "r"(a[1]), "r"(a[2]), "r"(a[3]), "r"(b[0]), "r"(b[1]));
}
__device__ __forceinline__ void red_add_v2(float* p, float a, float b) {
    asm volatile("red.global.add.v2.f32 [%0], {%1, %2};" :: "l"(p), "f"(a), "f"(b) : "memory");
}
__device__ __forceinline__ void red_add_v4(float* p, float a, float b, float c, float d) {
    asm volatile("red.global.add.v4.f32 [%0], {%1, %2, %3, %4};"
                 :: "l"(p), "f"(a), "f"(b), "f"(c), "f"(d) : "memory");
}
// hp = bf16x2(a lo-half, b hi-half); lp = residuals
__device__ __forceinline__ void split2(float a, float b, uint32_t& hp, uint32_t& lp) {
    asm("cvt.rn.bf16x2.f32 %0, %1, %2;" : "=r"(hp) : "f"(b), "f"(a));
    float ha = __uint_as_float(hp << 16);
    float hb = __uint_as_float(hp & 0xFFFF0000u);
    asm("cvt.rn.bf16x2.f32 %0, %1, %2;" : "=r"(lp) : "f"(b - hb), "f"(a - ha));
}

// ---------------------------------------------------------------------------
__global__ void init_kernel(const float* __restrict__ x, float* __restrict__ out) {
    int i = blockIdx.x * blockDim.x + threadIdx.x;
    if (i < N_NODES * DD) { g_aggr[i] = 0.1f * x[i]; out[i] = 0.0f; }
}

__global__ void scatter_kernel(const float* __restrict__ x, const int* __restrict__ eidx,
                               const int* __restrict__ rid, const int* __restrict__ neg,
                               const float* __restrict__ rel) {
    int gw = (blockIdx.x * blockDim.x + threadIdx.x) >> 5;
    int lane = threadIdx.x & 31;
    if (gw >= N_EDGES) return;
    int src = eidx[gw], dst = eidx[N_EDGES + gw], r = rid[gw];
    float coef = 1.0f - 2.0f * (float)neg[gw];
    float4 xv = ((const float4*)(x + (size_t)src * DD))[lane];
    float4 rv = ((const float4*)(rel + (size_t)r * DD))[lane];
    red_add_v4(g_aggr + (size_t)dst * DD + lane * 4,
               (xv.x + rv.x) * coef, (xv.y + rv.y) * coef,
               (xv.z + rv.z) * coef, (xv.w + rv.w) * coef);
}

__global__ void prep_kernel(const float* __restrict__ eemb) {
    int i = blockIdx.x * blockDim.x + threadIdx.x;    // over N_ENT*64 float2
    if (i >= N_ENT * (DD / 2)) return;
    float2 v = ((const float2*)eemb)[i];
    uint32_t hp, lp; split2(v.x, v.y, hp, lp);
    ((uint32_t*)g_Ehi)[i] = hp;
    ((uint32_t*)g_Elo)[i] = lp;
}

// ---------------------------------------------------------------------------
__global__ void __launch_bounds__(NTHR, 2)
gemm_fused(const float* __restrict__ scal, const float* __restrict__ bias,
           float* __restrict__ out) {
    extern __shared__ char smem[];
    const uint32_t sb = s2u(smem);
    const int tid = threadIdx.x, wid = tid >> 5, lane = tid & 31;
    const int mt = blockIdx.x & (MTILES - 1), sp = blockIdx.x / MTILES;
    const int m0 = mt * BM;
    const int t0 = sp * TPS, t1 = min(NVT, t0 + TPS);
    if (t0 >= t1) return;

    const int wm = wid * 16;               // warp owns rows [wm, wm+16)

    auto load_tiles = [&](int t, int b) {
        const int v0 = t * BV;
        const uint32_t eb = sb + SM_EB + b * EB_STRIDE;
        for (int i = tid; i < 1024; i += NTHR) {    // E [64v,128d] hi/lo, 16B chunks
            int v = i >> 4, dg = (i & 15) * 8;
            int gv = v0 + v;
            uint32_t o = off128(v, dg);
            int sz = (gv < N_ENT) ? 16 : 0;
            const void* pH = sz ? (const void*)(g_Ehi + (size_t)gv * DD + dg) : (const void*)g_Ehi;
            const void* pL = sz ? (const void*)(g_Elo + (size_t)gv * DD + dg) : (const void*)g_Elo;
            cpa16(eb + EB_HI + o, pH, sz);
            cpa16(eb + EB_LO + o, pL, sz);
        }
        if (tid < 32) {                              // 64 scale + 64 bias f32
            int half = tid >> 4, g = tid & 15;
            int gv = v0 + g * 4;
            int rem = N_ENT - gv;
            int sz = rem >= 4 ? 16 : (rem > 0 ? rem * 4 : 0);
            const float* src = half ? bias : scal;
            const void* p = sz ? (const void*)(src + gv) : (const void*)src;
            cpa16(eb + EB_SCB + half * 256 + g * 16, p, sz);
        }
    };

    // issue tile-0 E loads first so they overlap the A staging below
    load_tiles(t0, 0);
    cpa_commit();

    // ---- A tile: g_aggr f32 -> hi/lo bf16, swizzled (staged once) ----
    for (int i = tid; i < BM * (DD / 4); i += NTHR) {
        int m = i >> 5, k = (i & 31) * 4;
        float4 a = *(const float4*)(g_aggr + (size_t)(m0 + m) * DD + k);
        uint32_t h01, l01, h23, l23;
        split2(a.x, a.y, h01, l01);
        split2(a.z, a.w, h23, l23);
        uint32_t o0 = off128(m, k), o1 = off128(m, k + 2);
        *(uint32_t*)(smem + SM_AHI + o0) = h01; *(uint32_t*)(smem + SM_AHI + o1) = h23;
        *(uint32_t*)(smem + SM_ALO + o0) = l01; *(uint32_t*)(smem + SM_ALO + o1) = l23;
    }
    __syncthreads();

    // per-lane ldmatrix pieces (constant across loop)
    const int lr16 = lane & 15;            // row within 16
    const int lc8  = (lane >> 4) << 3;     // +8 col for upper half-warp
    const int lrB  = (lane & 7) | ((lane & 16) >> 1);  // B non-trans row
    const int lcB  = lane & 8;                          // B non-trans col sel
    const int ce   = (lane & 3) * 2;       // C/epilogue col pair base

    // ---- hoist ALL GEMM1 A fragments into registers (invariant over tiles) --
    uint32_t fAh[8][4], fAl[8][4];
    #pragma unroll
    for (int ks = 0; ks < 8; ks++) {
        uint32_t o = off128(wm + lr16, ks * 16 + lc8);
        ldm4(fAh[ks][0], fAh[ks][1], fAh[ks][2], fAh[ks][3], sb + SM_AHI + o);
        ldm4(fAl[ks][0], fAl[ks][1], fAl[ks][2], fAl[ks][3], sb + SM_ALO + o);
    }

    float accO[16][4];                      // 16m x 128d per warp
    #pragma unroll
    for (int nt = 0; nt < 16; nt++)
        #pragma unroll
        for (int q = 0; q < 4; q++) accO[nt][q] = 0.0f;

    for (int t = t0; t < t1; ++t) {
        const int buf = (t - t0) & 1;
        const uint32_t eb = sb + SM_EB + buf * EB_STRIDE;

        cpa_wait0();           // tile t landed (this thread's copies)
        __syncthreads();       // visible to all; all warps done with buf^1
        if (t + 1 < t1) { load_tiles(t + 1, buf ^ 1); cpa_commit(); }

        // ---------------- GEMM1: S[16m x 64v] per warp (3 split passes) ------
        float accS[8][4];
        #pragma unroll
        for (int nt = 0; nt < 8; nt++)
            #pragma unroll
            for (int q = 0; q < 4; q++) accS[nt][q] = 0.0f;

        #pragma unroll
        for (int ks = 0; ks < 8; ks++) {
            const int k0 = ks * 16;
            uint32_t bH[8][2], bL[8][2];
            #pragma unroll
            for (int ng = 0; ng < 4; ng++) {
                uint32_t o = off128(ng * 16 + lrB, k0 + lcB);
                uint32_t r0, r1, r2, r3;
                ldm4(r0, r1, r2, r3, eb + EB_HI + o);
                bH[ng * 2][0] = r0; bH[ng * 2][1] = r1;
                bH[ng * 2 + 1][0] = r2; bH[ng * 2 + 1][1] = r3;
                ldm4(r0, r1, r2, r3, eb + EB_LO + o);
                bL[ng * 2][0] = r0; bL[ng * 2][1] = r1;
                bL[ng * 2 + 1][0] = r2; bL[ng * 2 + 1][1] = r3;
            }
            #pragma unroll
            for (int nt = 0; nt < 8; nt++) {
                mma16816(accS[nt], fAh[ks], bH[nt]);
                mma16816(accS[nt], fAh[ks], bL[nt]);
                mma16816(accS[nt], fAl[ks], bH[nt]);
            }
        }

        // ------- epilogue in registers: relu(scale*s+bias) -> GEMM2 A frags --
        // C->A identity: a0=(r,k0k1), a1=(r+8,k0k1), a2=(r,k8k9), a3=(r+8,k8k9)
        uint32_t aSh[4][4], aSl[4][4];
        {
            const float* scb = (const float*)(smem + SM_EB + buf * EB_STRIDE + EB_SCB);
            #pragma unroll
            for (int nt = 0; nt < 8; nt++) {
                const int c = nt * 8 + ce;
                float2 scv = *(const float2*)(scb + c);
                float2 biv = *(const float2*)(scb + 64 + c);
                float v00 = fmaxf(fmaf(accS[nt][0], scv.x, biv.x), 0.f);
                float v01 = fmaxf(fmaf(accS[nt][1], scv.y, biv.y), 0.f);
                float v10 = fmaxf(fmaf(accS[nt][2], scv.x, biv.x), 0.f);
                float v11 = fmaxf(fmaf(accS[nt][3], scv.y, biv.y), 0.f);
                const int g = nt >> 1, sub = (nt & 1) * 2;
                split2(v00, v01, aSh[g][sub],     aSl[g][sub]);
                split2(v10, v11, aSh[g][sub + 1], aSl[g][sub + 1]);
            }
        }

        // ---------------- GEMM2: O[16m x 128d] += S' . E (3 split passes) ----
        #pragma unroll
        for (int g = 0; g < 4; g++) {          // k16 groups over v
            const int k0 = g * 16;
            #pragma unroll
            for (int half = 0; half < 2; half++) {
                uint32_t bH[8][2], bL[8][2];
                #pragma unroll
                for (int ng = 0; ng < 4; ng++) {
                    uint32_t o = off128(k0 + lr16, half * 64 + ng * 16 + lc8);
                    uint32_t r0, r1, r2, r3;
                    ldm4t(r0, r1, r2, r3, eb + EB_HI + o);
                    bH[ng * 2][0] = r0; bH[ng * 2][1] = r1;
                    bH[ng * 2 + 1][0] = r2; bH[ng * 2 + 1][1] = r3;
                    ldm4t(r0, r1, r2, r3, eb + EB_LO + o);
                    bL[ng * 2][0] = r0; bL[ng * 2][1] = r1;
                    bL[ng * 2 + 1][0] = r2; bL[ng * 2 + 1][1] = r3;
                }
                #pragma unroll
                for (int ng = 0; ng < 8; ng++) {
                    float* d = accO[half * 8 + ng];
                    mma16816(d, aSh[g], bH[ng]);
                    mma16816(d, aSh[g], bL[ng]);
                    mma16816(d, aSl[g], bH[ng]);
                }
            }
        }
    }

    // ---- flush O to out (+= across splits) ----
    {
        const int r0 = m0 + wm + (lane >> 2);
        #pragma unroll
        for (int nt = 0; nt < 16; nt++) {
            const int c = nt * 8 + ce;
            red_add_v2(out + (size_t)r0 * DD + c,       accO[nt][0], accO[nt][1]);
            red_add_v2(out + (size_t)(r0 + 8) * DD + c, accO[nt][2], accO[nt][3]);
        }
    }
}

// ---------------------------------------------------------------------------
extern "C" void kernel_launch(void* const* d_in, const int* in_sizes, int n_in,
                              void* d_out, int out_size) {
    const float* x     = (const float*)d_in[0];
    const int*   eidx  = (const int*)  d_in[1];
    const int*   rid   = (const int*)  d_in[2];
    const int*   neg   = (const int*)  d_in[3];
    const float* rel   = (const float*)d_in[4];
    const float* eemb  = (const float*)d_in[5];
    const float* scale = (const float*)d_in[6];
    const float* bias  = (const float*)d_in[7];
    float* out = (float*)d_out;

    cudaFuncSetAttribute(gemm_fused, cudaFuncAttributeMaxDynamicSharedMemorySize, SMEM_BYTES);

    prep_kernel<<<(N_ENT * (DD / 2) + 255) / 256, 256>>>(eemb);
    init_kernel<<<(N_NODES * DD + 255) / 256, 256>>>(x, out);
    scatter_kernel<<<N_EDGES * 32 / 256, 256>>>(x, eidx, rid, neg, rel);
    gemm_fused<<<MTILES * NSPLIT, NTHR, SMEM_BYTES>>>(scale, bias, out);
}

// round 9
// speedup vs baseline: 6.8714x; 1.3828x over previous
#include <cuda_runtime.h>
#include <cuda_fp16.h>
#include <cstdint>

// ---------------------------------------------------------------------------
// LMPNN round 9: fp16 a-split-2 / b-plain fused double-GEMM.
// A and S' carried as fp16 hi+lo (a-side ~exact); E plain fp16 (err ~2^-12).
// 2 MMAs per k-step per GEMM (was 3 with bf16x3), single E buffer.
// ---------------------------------------------------------------------------

#define DD 128
static constexpr int N_NODES = 4096;
static constexpr int N_EDGES = 262144;
static constexpr int N_ENT   = 50000;

static constexpr int BM = 64;
static constexpr int BV = 64;
static constexpr int NVT = (N_ENT + BV - 1) / BV;        // 782
static constexpr int NSPLIT = 9;
static constexpr int TPS = (NVT + NSPLIT - 1) / NSPLIT;  // 87
static constexpr int MTILES = N_NODES / BM;              // 64
static constexpr int NTHR = 128;                         // 4 warps

__device__ float  g_aggr[N_NODES * DD];
__device__ __half g_Eh[(size_t)N_ENT * DD];

// ---- smem map (bytes) ------------------------------------------------------
static constexpr int SM_AHI = 0;          // 16384  A_hi [64m,128k] fp16
static constexpr int SM_ALO = 16384;      // 16384  A_lo
static constexpr int SM_EB  = 32768;      // 2 bufs x 16896
static constexpr int EB_E   = 0;          // 16384  E [64v,128d] fp16
static constexpr int EB_SCB = 16384;      // 512 (64 scale f32 + 64 bias f32)
static constexpr int EB_STRIDE = 16896;
static constexpr int SMEM_BYTES = 32768 + 2 * EB_STRIDE;  // 66560

// ---------------------------------------------------------------------------
__device__ __forceinline__ uint32_t s2u(const void* p) {
    uint32_t a;
    asm("{ .reg .u64 t; cvta.to.shared.u64 t, %1; cvt.u32.u64 %0, t; }" : "=r"(a) : "l"(p));
    return a;
}
// swizzled offsets: 16B chunks XOR'ed by (row & 7)
__device__ __forceinline__ uint32_t off128(int r, int c) {   // 128 f16/row
    return (uint32_t)(r * 256) + ((((c >> 3) ^ (r & 7)) << 4) | ((c & 7) * 2));
}
__device__ __forceinline__ void cpa16(uint32_t dst, const void* src, int srcsize) {
    asm volatile("cp.async.cg.shared.global [%0], [%1], 16, %2;"
                 :: "r"(dst), "l"(src), "r"(srcsize) : "memory");
}
__device__ __forceinline__ void cpa_commit() { asm volatile("cp.async.commit_group;" ::: "memory"); }
__device__ __forceinline__ void cpa_wait0()  { asm volatile("cp.async.wait_group 0;"  ::: "memory"); }

__device__ __forceinline__ void ldm4(uint32_t& r0, uint32_t& r1, uint32_t& r2, uint32_t& r3, uint32_t a) {
    asm volatile("ldmatrix.sync.aligned.m8n8.x4.shared.b16 {%0,%1,%2,%3}, [%4];"
                 : "=r"(r0), "=r"(r1), "=r"(r2), "=r"(r3) : "r"(a));
}
__device__ __forceinline__ void ldm4t(uint32_t& r0, uint32_t& r1, uint32_t& r2, uint32_t& r3, uint32_t a) {
    asm volatile("ldmatrix.sync.aligned.m8n8.x4.trans.shared.b16 {%0,%1,%2,%3}, [%4];"
                 : "=r"(r0), "=r"(r1), "=r"(r2), "=r"(r3) : "r"(a));
}
__device__ __forceinline__ void mma16816h(float* d, const uint32_t* a, const uint32_t* b) {
    asm volatile("mma.sync.aligned.m16n8k16.row.col.f32.f16.f16.f32 "
                 "{%0,%1,%2,%3}, {%4,%5,%6,%7}, {%8,%9}, {%0,%1,%2,%3};"
                 : "+f"(d[0]), "+f"(d[1]), "+f"(d[2]), "+f"(d[3])
                 : "r"(a[0]), "r"(a[1]), "r"(a[2]), "r"(a[3]), "r"(b[0]), "r"(b[1]));
}
__device__ __forceinline__ void red_add_v2(float* p, float a, float b) {
    asm volatile("red.global.add.v2.f32 [%0], {%1, %2};" :: "l"(p), "f"(a), "f"(b) : "memory");
}
__device__ __forceinline__ void red_add_v4(float* p, float a, float b, float c, float d) {
    asm volatile("red.global.add.v4.f32 [%0], {%1, %2, %3, %4};"
                 :: "l"(p), "f"(a), "f"(b), "f"(c), "f"(d) : "memory");
}
// hp = f16x2{lo: a, hi: b}; lp = f16x2 residuals (a-side split-2, ~exact)
__device__ __forceinline__ void split2h(float a, float b, uint32_t& hp, uint32_t& lp) {
    asm("cvt.rn.f16x2.f32 %0, %1, %2;" : "=r"(hp) : "f"(b), "f"(a));
    __half2 h = *reinterpret_cast<__half2*>(&hp);
    float2 hf = __half22float2(h);
    asm("cvt.rn.f16x2.f32 %0, %1, %2;" : "=r"(lp) : "f"(b - hf.y), "f"(a - hf.x));
}

// ---------------------------------------------------------------------------
__global__ void init_kernel(const float* __restrict__ x, float* __restrict__ out) {
    int i = blockIdx.x * blockDim.x + threadIdx.x;
    if (i < N_NODES * DD) { g_aggr[i] = 0.1f * x[i]; out[i] = 0.0f; }
}

__global__ void scatter_kernel(const float* __restrict__ x, const int* __restrict__ eidx,
                               const int* __restrict__ rid, const int* __restrict__ neg,
                               const float* __restrict__ rel) {
    int gw = (blockIdx.x * blockDim.x + threadIdx.x) >> 5;
    int lane = threadIdx.x & 31;
    if (gw >= N_EDGES) return;
    int src = eidx[gw], dst = eidx[N_EDGES + gw], r = rid[gw];
    float coef = 1.0f - 2.0f * (float)neg[gw];
    float4 xv = ((const float4*)(x + (size_t)src * DD))[lane];
    float4 rv = ((const float4*)(rel + (size_t)r * DD))[lane];
    red_add_v4(g_aggr + (size_t)dst * DD + lane * 4,
               (xv.x + rv.x) * coef, (xv.y + rv.y) * coef,
               (xv.z + rv.z) * coef, (xv.w + rv.w) * coef);
}

__global__ void prep_kernel(const float* __restrict__ eemb) {
    int i = blockIdx.x * blockDim.x + threadIdx.x;    // over N_ENT*64 float2
    if (i >= N_ENT * (DD / 2)) return;
    float2 v = ((const float2*)eemb)[i];
    uint32_t hp;
    asm("cvt.rn.f16x2.f32 %0, %1, %2;" : "=r"(hp) : "f"(v.y), "f"(v.x));
    ((uint32_t*)g_Eh)[i] = hp;
}

// ---------------------------------------------------------------------------
__global__ void __launch_bounds__(NTHR, 2)
gemm_fused(const float* __restrict__ scal, const float* __restrict__ bias,
           float* __restrict__ out) {
    extern __shared__ char smem[];
    const uint32_t sb = s2u(smem);
    const int tid = threadIdx.x, wid = tid >> 5, lane = tid & 31;
    const int mt = blockIdx.x & (MTILES - 1), sp = blockIdx.x / MTILES;
    const int m0 = mt * BM;
    const int t0 = sp * TPS, t1 = min(NVT, t0 + TPS);
    if (t0 >= t1) return;

    const int wm = wid * 16;               // warp owns rows [wm, wm+16)

    auto load_tiles = [&](int t, int b) {
        const int v0 = t * BV;
        const uint32_t eb = sb + SM_EB + b * EB_STRIDE;
        for (int i = tid; i < 1024; i += NTHR) {    // E [64v,128d] fp16, 16B chunks
            int v = i >> 4, dg = (i & 15) * 8;
            int gv = v0 + v;
            uint32_t o = off128(v, dg);
            int sz = (gv < N_ENT) ? 16 : 0;
            const void* pE = sz ? (const void*)(g_Eh + (size_t)gv * DD + dg) : (const void*)g_Eh;
            cpa16(eb + EB_E + o, pE, sz);
        }
        if (tid < 32) {                              // 64 scale + 64 bias f32
            int half = tid >> 4, g = tid & 15;
            int gv = v0 + g * 4;
            int rem = N_ENT - gv;
            int sz = rem >= 4 ? 16 : (rem > 0 ? rem * 4 : 0);
            const float* src = half ? bias : scal;
            const void* p = sz ? (const void*)(src + gv) : (const void*)src;
            cpa16(eb + EB_SCB + half * 256 + g * 16, p, sz);
        }
    };

    // issue tile-0 E loads first so they overlap the A staging below
    load_tiles(t0, 0);
    cpa_commit();

    // ---- A tile: g_aggr f32 -> fp16 hi/lo, swizzled (staged once) ----
    for (int i = tid; i < BM * (DD / 4); i += NTHR) {
        int m = i >> 5, k = (i & 31) * 4;
        float4 a = *(const float4*)(g_aggr + (size_t)(m0 + m) * DD + k);
        uint32_t h01, l01, h23, l23;
        split2h(a.x, a.y, h01, l01);
        split2h(a.z, a.w, h23, l23);
        uint32_t o0 = off128(m, k), o1 = off128(m, k + 2);
        *(uint32_t*)(smem + SM_AHI + o0) = h01; *(uint32_t*)(smem + SM_AHI + o1) = h23;
        *(uint32_t*)(smem + SM_ALO + o0) = l01; *(uint32_t*)(smem + SM_ALO + o1) = l23;
    }
    __syncthreads();

    // per-lane ldmatrix pieces (constant across loop)
    const int lr16 = lane & 15;            // row within 16
    const int lc8  = (lane >> 4) << 3;     // +8 col for upper half-warp
    const int lrB  = (lane & 7) | ((lane & 16) >> 1);  // B non-trans row
    const int lcB  = lane & 8;                          // B non-trans col sel
    const int ce   = (lane & 3) * 2;       // C/epilogue col pair base

    // ---- hoist ALL GEMM1 A fragments into registers (invariant over tiles) --
    uint32_t fAh[8][4], fAl[8][4];
    #pragma unroll
    for (int ks = 0; ks < 8; ks++) {
        uint32_t o = off128(wm + lr16, ks * 16 + lc8);
        ldm4(fAh[ks][0], fAh[ks][1], fAh[ks][2], fAh[ks][3], sb + SM_AHI + o);
        ldm4(fAl[ks][0], fAl[ks][1], fAl[ks][2], fAl[ks][3], sb + SM_ALO + o);
    }

    float accO[16][4];                      // 16m x 128d per warp
    #pragma unroll
    for (int nt = 0; nt < 16; nt++)
        #pragma unroll
        for (int q = 0; q < 4; q++) accO[nt][q] = 0.0f;

    for (int t = t0; t < t1; ++t) {
        const int buf = (t - t0) & 1;
        const uint32_t eb = sb + SM_EB + buf * EB_STRIDE;

        cpa_wait0();           // tile t landed (this thread's copies)
        __syncthreads();       // visible to all; all warps done with buf^1
        if (t + 1 < t1) { load_tiles(t + 1, buf ^ 1); cpa_commit(); }

        // ---------------- GEMM1: S[16m x 64v] per warp (2 split passes) ------
        float accS[8][4];
        #pragma unroll
        for (int nt = 0; nt < 8; nt++)
            #pragma unroll
            for (int q = 0; q < 4; q++) accS[nt][q] = 0.0f;

        #pragma unroll
        for (int ks = 0; ks < 8; ks++) {
            const int k0 = ks * 16;
            uint32_t bF[8][2];
            #pragma unroll
            for (int ng = 0; ng < 4; ng++) {
                uint32_t o = off128(ng * 16 + lrB, k0 + lcB);
                uint32_t r0, r1, r2, r3;
                ldm4(r0, r1, r2, r3, eb + EB_E + o);
                bF[ng * 2][0] = r0; bF[ng * 2][1] = r1;
                bF[ng * 2 + 1][0] = r2; bF[ng * 2 + 1][1] = r3;
            }
            #pragma unroll
            for (int nt = 0; nt < 8; nt++) {
                mma16816h(accS[nt], fAh[ks], bF[nt]);
                mma16816h(accS[nt], fAl[ks], bF[nt]);
            }
        }

        // ------- epilogue in registers: relu(scale*s+bias) -> GEMM2 A frags --
        // C->A identity: a0=(r,k0k1), a1=(r+8,k0k1), a2=(r,k8k9), a3=(r+8,k8k9)
        uint32_t aSh[4][4], aSl[4][4];
        {
            const float* scb = (const float*)(smem + SM_EB + buf * EB_STRIDE + EB_SCB);
            #pragma unroll
            for (int nt = 0; nt < 8; nt++) {
                const int c = nt * 8 + ce;
                float2 scv = *(const float2*)(scb + c);
                float2 biv = *(const float2*)(scb + 64 + c);
                float v00 = fmaxf(fmaf(accS[nt][0], scv.x, biv.x), 0.f);
                float v01 = fmaxf(fmaf(accS[nt][1], scv.y, biv.y), 0.f);
                float v10 = fmaxf(fmaf(accS[nt][2], scv.x, biv.x), 0.f);
                float v11 = fmaxf(fmaf(accS[nt][3], scv.y, biv.y), 0.f);
                const int g = nt >> 1, sub = (nt & 1) * 2;
                split2h(v00, v01, aSh[g][sub],     aSl[g][sub]);
                split2h(v10, v11, aSh[g][sub + 1], aSl[g][sub + 1]);
            }
        }

        // ---------------- GEMM2: O[16m x 128d] += S' . E (2 split passes) ----
        #pragma unroll
        for (int g = 0; g < 4; g++) {          // k16 groups over v
            const int k0 = g * 16;
            #pragma unroll
            for (int half = 0; half < 2; half++) {
                uint32_t bF[8][2];
                #pragma unroll
                for (int ng = 0; ng < 4; ng++) {
                    uint32_t o = off128(k0 + lr16, half * 64 + ng * 16 + lc8);
                    uint32_t r0, r1, r2, r3;
                    ldm4t(r0, r1, r2, r3, eb + EB_E + o);
                    bF[ng * 2][0] = r0; bF[ng * 2][1] = r1;
                    bF[ng * 2 + 1][0] = r2; bF[ng * 2 + 1][1] = r3;
                }
                #pragma unroll
                for (int ng = 0; ng < 8; ng++) {
                    float* d = accO[half * 8 + ng];
                    mma16816h(d, aSh[g], bF[ng]);
                    mma16816h(d, aSl[g], bF[ng]);
                }
            }
        }
    }

    // ---- flush O to out (+= across splits) ----
    {
        const int r0 = m0 + wm + (lane >> 2);
        #pragma unroll
        for (int nt = 0; nt < 16; nt++) {
            const int c = nt * 8 + ce;
            red_add_v2(out + (size_t)r0 * DD + c,       accO[nt][0], accO[nt][1]);
            red_add_v2(out + (size_t)(r0 + 8) * DD + c, accO[nt][2], accO[nt][3]);
        }
    }
}

// ---------------------------------------------------------------------------
extern "C" void kernel_launch(void* const* d_in, const int* in_sizes, int n_in,
                              void* d_out, int out_size) {
    const float* x     = (const float*)d_in[0];
    const int*   eidx  = (const int*)  d_in[1];
    const int*   rid   = (const int*)  d_in[2];
    const int*   neg   = (const int*)  d_in[3];
    const float* rel   = (const float*)d_in[4];
    const float* eemb  = (const float*)d_in[5];
    const float* scale = (const float*)d_in[6];
    const float* bias  = (const float*)d_in[7];
    float* out = (float*)d_out;

    cudaFuncSetAttribute(gemm_fused, cudaFuncAttributeMaxDynamicSharedMemorySize, SMEM_BYTES);

    prep_kernel<<<(N_ENT * (DD / 2) + 255) / 256, 256>>>(eemb);
    init_kernel<<<(N_NODES * DD + 255) / 256, 256>>>(x, out);
    scatter_kernel<<<N_EDGES * 32 / 256, 256>>>(x, eidx, rid, neg, rel);
    gemm_fused<<<MTILES * NSPLIT, NTHR, SMEM_BYTES>>>(scale, bias, out);
}

// round 10
// speedup vs baseline: 11.0936x; 1.6145x over previous
#include <cuda_runtime.h>
#include <cuda_fp16.h>
#include <cstdint>

// ---------------------------------------------------------------------------
// LMPNN round 10: plain fp16 fused double-GEMM (no splits).
// Calibration from R9: each independent fp16 rounding source contributes
// ~2.5e-5 to the norm rel_err -> plain fp16 everywhere lands ~5e-5..2.5e-4,
// well under the 1e-3 gate, at HALF the MMA count of R9.
// ---------------------------------------------------------------------------

#define DD 128
static constexpr int N_NODES = 4096;
static constexpr int N_EDGES = 262144;
static constexpr int N_ENT   = 50000;

static constexpr int BM = 64;
static constexpr int BV = 64;
static constexpr int NVT = (N_ENT + BV - 1) / BV;        // 782
static constexpr int NSPLIT = 9;
static constexpr int TPS = (NVT + NSPLIT - 1) / NSPLIT;  // 87
static constexpr int MTILES = N_NODES / BM;              // 64
static constexpr int NTHR = 128;                         // 4 warps

__device__ float  g_aggr[N_NODES * DD];
__device__ __half g_Eh[(size_t)N_ENT * DD];

// ---- smem map (bytes) ------------------------------------------------------
static constexpr int SM_A  = 0;           // 16384  A [64m,128k] fp16
static constexpr int SM_EB = 16384;       // 2 bufs x 16896
static constexpr int EB_E   = 0;          // 16384  E [64v,128d] fp16
static constexpr int EB_SCB = 16384;      // 512 (64 scale f32 + 64 bias f32)
static constexpr int EB_STRIDE = 16896;
static constexpr int SMEM_BYTES = 16384 + 2 * EB_STRIDE;  // 50176

// ---------------------------------------------------------------------------
__device__ __forceinline__ uint32_t s2u(const void* p) {
    uint32_t a;
    asm("{ .reg .u64 t; cvta.to.shared.u64 t, %1; cvt.u32.u64 %0, t; }" : "=r"(a) : "l"(p));
    return a;
}
// swizzled offsets: 16B chunks XOR'ed by (row & 7)
__device__ __forceinline__ uint32_t off128(int r, int c) {   // 128 f16/row
    return (uint32_t)(r * 256) + ((((c >> 3) ^ (r & 7)) << 4) | ((c & 7) * 2));
}
__device__ __forceinline__ void cpa16(uint32_t dst, const void* src, int srcsize) {
    asm volatile("cp.async.cg.shared.global [%0], [%1], 16, %2;"
                 :: "r"(dst), "l"(src), "r"(srcsize) : "memory");
}
__device__ __forceinline__ void cpa_commit() { asm volatile("cp.async.commit_group;" ::: "memory"); }
__device__ __forceinline__ void cpa_wait0()  { asm volatile("cp.async.wait_group 0;"  ::: "memory"); }

__device__ __forceinline__ void ldm4(uint32_t& r0, uint32_t& r1, uint32_t& r2, uint32_t& r3, uint32_t a) {
    asm volatile("ldmatrix.sync.aligned.m8n8.x4.shared.b16 {%0,%1,%2,%3}, [%4];"
                 : "=r"(r0), "=r"(r1), "=r"(r2), "=r"(r3) : "r"(a));
}
__device__ __forceinline__ void ldm4t(uint32_t& r0, uint32_t& r1, uint32_t& r2, uint32_t& r3, uint32_t a) {
    asm volatile("ldmatrix.sync.aligned.m8n8.x4.trans.shared.b16 {%0,%1,%2,%3}, [%4];"
                 : "=r"(r0), "=r"(r1), "=r"(r2), "=r"(r3) : "r"(a));
}
__device__ __forceinline__ void mma16816h(float* d, const uint32_t* a, const uint32_t* b) {
    asm volatile("mma.sync.aligned.m16n8k16.row.col.f32.f16.f16.f32 "
                 "{%0,%1,%2,%3}, {%4,%5,%6,%7}, {%8,%9}, {%0,%1,%2,%3};"
                 : "+f"(d[0]), "+f"(d[1]), "+f"(d[2]), "+f"(d[3])
                 : "r"(a[0]), "r"(a[1]), "r"(a[2]), "r"(a[3]), "r"(b[0]), "r"(b[1]));
}
__device__ __forceinline__ void red_add_v2(float* p, float a, float b) {
    asm volatile("red.global.add.v2.f32 [%0], {%1, %2};" :: "l"(p), "f"(a), "f"(b) : "memory");
}
__device__ __forceinline__ void red_add_v4(float* p, float a, float b, float c, float d) {
    asm volatile("red.global.add.v4.f32 [%0], {%1, %2, %3, %4};"
                 :: "l"(p), "f"(a), "f"(b), "f"(c), "f"(d) : "memory");
}
__device__ __forceinline__ uint32_t pack_h2(float a, float b) {
    uint32_t p;
    asm("cvt.rn.f16x2.f32 %0, %1, %2;" : "=r"(p) : "f"(b), "f"(a));
    return p;
}

// ---------------------------------------------------------------------------
__global__ void init_kernel(const float* __restrict__ x, float* __restrict__ out) {
    int i = blockIdx.x * blockDim.x + threadIdx.x;
    if (i < N_NODES * DD) { g_aggr[i] = 0.1f * x[i]; out[i] = 0.0f; }
}

__global__ void scatter_kernel(const float* __restrict__ x, const int* __restrict__ eidx,
                               const int* __restrict__ rid, const int* __restrict__ neg,
                               const float* __restrict__ rel) {
    int gw = (blockIdx.x * blockDim.x + threadIdx.x) >> 5;
    int lane = threadIdx.x & 31;
    if (gw >= N_EDGES) return;
    int src = eidx[gw], dst = eidx[N_EDGES + gw], r = rid[gw];
    float coef = 1.0f - 2.0f * (float)neg[gw];
    float4 xv = ((const float4*)(x + (size_t)src * DD))[lane];
    float4 rv = ((const float4*)(rel + (size_t)r * DD))[lane];
    red_add_v4(g_aggr + (size_t)dst * DD + lane * 4,
               (xv.x + rv.x) * coef, (xv.y + rv.y) * coef,
               (xv.z + rv.z) * coef, (xv.w + rv.w) * coef);
}

__global__ void prep_kernel(const float* __restrict__ eemb) {
    int i = blockIdx.x * blockDim.x + threadIdx.x;    // over N_ENT*64 float2
    if (i >= N_ENT * (DD / 2)) return;
    float2 v = ((const float2*)eemb)[i];
    ((uint32_t*)g_Eh)[i] = pack_h2(v.x, v.y);
}

// ---------------------------------------------------------------------------
__global__ void __launch_bounds__(NTHR, 2)
gemm_fused(const float* __restrict__ scal, const float* __restrict__ bias,
           float* __restrict__ out) {
    extern __shared__ char smem[];
    const uint32_t sb = s2u(smem);
    const int tid = threadIdx.x, wid = tid >> 5, lane = tid & 31;
    const int mt = blockIdx.x & (MTILES - 1), sp = blockIdx.x / MTILES;
    const int m0 = mt * BM;
    const int t0 = sp * TPS, t1 = min(NVT, t0 + TPS);
    if (t0 >= t1) return;

    const int wm = wid * 16;               // warp owns rows [wm, wm+16)

    auto load_tiles = [&](int t, int b) {
        const int v0 = t * BV;
        const uint32_t eb = sb + SM_EB + b * EB_STRIDE;
        for (int i = tid; i < 1024; i += NTHR) {    // E [64v,128d] fp16, 16B chunks
            int v = i >> 4, dg = (i & 15) * 8;
            int gv = v0 + v;
            uint32_t o = off128(v, dg);
            int sz = (gv < N_ENT) ? 16 : 0;
            const void* pE = sz ? (const void*)(g_Eh + (size_t)gv * DD + dg) : (const void*)g_Eh;
            cpa16(eb + EB_E + o, pE, sz);
        }
        if (tid < 32) {                              // 64 scale + 64 bias f32
            int half = tid >> 4, g = tid & 15;
            int gv = v0 + g * 4;
            int rem = N_ENT - gv;
            int sz = rem >= 4 ? 16 : (rem > 0 ? rem * 4 : 0);
            const float* src = half ? bias : scal;
            const void* p = sz ? (const void*)(src + gv) : (const void*)src;
            cpa16(eb + EB_SCB + half * 256 + g * 16, p, sz);
        }
    };

    // issue tile-0 E loads first so they overlap the A staging below
    load_tiles(t0, 0);
    cpa_commit();

    // ---- A tile: g_aggr f32 -> fp16, swizzled (staged once) ----
    for (int i = tid; i < BM * (DD / 4); i += NTHR) {
        int m = i >> 5, k = (i & 31) * 4;
        float4 a = *(const float4*)(g_aggr + (size_t)(m0 + m) * DD + k);
        *(uint32_t*)(smem + SM_A + off128(m, k))     = pack_h2(a.x, a.y);
        *(uint32_t*)(smem + SM_A + off128(m, k + 2)) = pack_h2(a.z, a.w);
    }
    __syncthreads();

    // per-lane ldmatrix pieces (constant across loop)
    const int lr16 = lane & 15;            // row within 16
    const int lc8  = (lane >> 4) << 3;     // +8 col for upper half-warp
    const int lrB  = (lane & 7) | ((lane & 16) >> 1);  // B non-trans row
    const int lcB  = lane & 8;                          // B non-trans col sel
    const int ce   = (lane & 3) * 2;       // C/epilogue col pair base

    // ---- hoist ALL GEMM1 A fragments into registers (invariant over tiles) --
    uint32_t fA[8][4];
    #pragma unroll
    for (int ks = 0; ks < 8; ks++) {
        uint32_t o = off128(wm + lr16, ks * 16 + lc8);
        ldm4(fA[ks][0], fA[ks][1], fA[ks][2], fA[ks][3], sb + SM_A + o);
    }

    float accO[16][4];                      // 16m x 128d per warp
    #pragma unroll
    for (int nt = 0; nt < 16; nt++)
        #pragma unroll
        for (int q = 0; q < 4; q++) accO[nt][q] = 0.0f;

    for (int t = t0; t < t1; ++t) {
        const int buf = (t - t0) & 1;
        const uint32_t eb = sb + SM_EB + buf * EB_STRIDE;

        cpa_wait0();           // tile t landed (this thread's copies)
        __syncthreads();       // visible to all; all warps done with buf^1
        if (t + 1 < t1) { load_tiles(t + 1, buf ^ 1); cpa_commit(); }

        // ---------------- GEMM1: S[16m x 64v] per warp ----------------------
        float accS[8][4];
        #pragma unroll
        for (int nt = 0; nt < 8; nt++)
            #pragma unroll
            for (int q = 0; q < 4; q++) accS[nt][q] = 0.0f;

        #pragma unroll
        for (int ks = 0; ks < 8; ks++) {
            const int k0 = ks * 16;
            uint32_t bF[8][2];
            #pragma unroll
            for (int ng = 0; ng < 4; ng++) {
                uint32_t o = off128(ng * 16 + lrB, k0 + lcB);
                uint32_t r0, r1, r2, r3;
                ldm4(r0, r1, r2, r3, eb + EB_E + o);
                bF[ng * 2][0] = r0; bF[ng * 2][1] = r1;
                bF[ng * 2 + 1][0] = r2; bF[ng * 2 + 1][1] = r3;
            }
            #pragma unroll
            for (int nt = 0; nt < 8; nt++)
                mma16816h(accS[nt], fA[ks], bF[nt]);
        }

        // ------- epilogue in registers: relu(scale*s+bias) -> GEMM2 A frags --
        // C->A identity: a0=(r,k0k1), a1=(r+8,k0k1), a2=(r,k8k9), a3=(r+8,k8k9)
        uint32_t aS[4][4];
        {
            const float* scb = (const float*)(smem + SM_EB + buf * EB_STRIDE + EB_SCB);
            #pragma unroll
            for (int nt = 0; nt < 8; nt++) {
                const int c = nt * 8 + ce;
                float2 scv = *(const float2*)(scb + c);
                float2 biv = *(const float2*)(scb + 64 + c);
                float v00 = fmaxf(fmaf(accS[nt][0], scv.x, biv.x), 0.f);
                float v01 = fmaxf(fmaf(accS[nt][1], scv.y, biv.y), 0.f);
                float v10 = fmaxf(fmaf(accS[nt][2], scv.x, biv.x), 0.f);
                float v11 = fmaxf(fmaf(accS[nt][3], scv.y, biv.y), 0.f);
                const int g = nt >> 1, sub = (nt & 1) * 2;
                aS[g][sub]     = pack_h2(v00, v01);
                aS[g][sub + 1] = pack_h2(v10, v11);
            }
        }

        // ---------------- GEMM2: O[16m x 128d] += S' . E ---------------------
        #pragma unroll
        for (int g = 0; g < 4; g++) {          // k16 groups over v
            const int k0 = g * 16;
            #pragma unroll
            for (int half = 0; half < 2; half++) {
                uint32_t bF[8][2];
                #pragma unroll
                for (int ng = 0; ng < 4; ng++) {
                    uint32_t o = off128(k0 + lr16, half * 64 + ng * 16 + lc8);
                    uint32_t r0, r1, r2, r3;
                    ldm4t(r0, r1, r2, r3, eb + EB_E + o);
                    bF[ng * 2][0] = r0; bF[ng * 2][1] = r1;
                    bF[ng * 2 + 1][0] = r2; bF[ng * 2 + 1][1] = r3;
                }
                #pragma unroll
                for (int ng = 0; ng < 8; ng++)
                    mma16816h(accO[half * 8 + ng], aS[g], bF[ng]);
            }
        }
    }

    // ---- flush O to out (+= across splits) ----
    {
        const int r0 = m0 + wm + (lane >> 2);
        #pragma unroll
        for (int nt = 0; nt < 16; nt++) {
            const int c = nt * 8 + ce;
            red_add_v2(out + (size_t)r0 * DD + c,       accO[nt][0], accO[nt][1]);
            red_add_v2(out + (size_t)(r0 + 8) * DD + c, accO[nt][2], accO[nt][3]);
        }
    }
}

// ---------------------------------------------------------------------------
extern "C" void kernel_launch(void* const* d_in, const int* in_sizes, int n_in,
                              void* d_out, int out_size) {
    const float* x     = (const float*)d_in[0];
    const int*   eidx  = (const int*)  d_in[1];
    const int*   rid   = (const int*)  d_in[2];
    const int*   neg   = (const int*)  d_in[3];
    const float* rel   = (const float*)d_in[4];
    const float* eemb  = (const float*)d_in[5];
    const float* scale = (const float*)d_in[6];
    const float* bias  = (const float*)d_in[7];
    float* out = (float*)d_out;

    cudaFuncSetAttribute(gemm_fused, cudaFuncAttributeMaxDynamicSharedMemorySize, SMEM_BYTES);

    prep_kernel<<<(N_ENT * (DD / 2) + 255) / 256, 256>>>(eemb);
    init_kernel<<<(N_NODES * DD + 255) / 256, 256>>>(x, out);
    scatter_kernel<<<N_EDGES * 32 / 256, 256>>>(x, eidx, rid, neg, rel);
    gemm_fused<<<MTILES * NSPLIT, NTHR, SMEM_BYTES>>>(scale, bias, out);
}

// round 11
// speedup vs baseline: 12.3270x; 1.1112x over previous
#include <cuda_runtime.h>
#include <cuda_fp16.h>
#include <cstdint>

// ---------------------------------------------------------------------------
// LMPNN round 11: plain fp16 fused double-GEMM, 2 m-tiles per warp (BM=128),
// fp16 accumulators in GEMM1 (D-frag == packed A-frag layout), f32 accO.
// MMA:LDSM ratio 2:1 -> 3.2:1; grid = one full 2-CTA/SM wave.
// ---------------------------------------------------------------------------

#define DD 128
static constexpr int N_NODES = 4096;
static constexpr int N_EDGES = 262144;
static constexpr int N_ENT   = 50000;

static constexpr int BM = 128;
static constexpr int BV = 64;
static constexpr int NVT = (N_ENT + BV - 1) / BV;        // 782
static constexpr int NSPLIT = 9;
static constexpr int TPS = (NVT + NSPLIT - 1) / NSPLIT;  // 87
static constexpr int MTILES = N_NODES / BM;              // 32
static constexpr int NTHR = 128;                         // 4 warps x 32 rows

__device__ float  g_aggr[N_NODES * DD];
__device__ __half g_Eh[(size_t)N_ENT * DD];

// ---- smem map (bytes) ------------------------------------------------------
static constexpr int SM_A  = 0;           // 32768  A [128m,128k] fp16
static constexpr int SM_EB = 32768;       // 2 bufs x 16896
static constexpr int EB_E   = 0;          // 16384  E [64v,128d] fp16
static constexpr int EB_SCB = 16384;      // 512 (64 scale f32 + 64 bias f32)
static constexpr int EB_STRIDE = 16896;
static constexpr int SMEM_BYTES = 32768 + 2 * EB_STRIDE;  // 66560; x2/SM ok

// ---------------------------------------------------------------------------
__device__ __forceinline__ uint32_t s2u(const void* p) {
    uint32_t a;
    asm("{ .reg .u64 t; cvta.to.shared.u64 t, %1; cvt.u32.u64 %0, t; }" : "=r"(a) : "l"(p));
    return a;
}
// swizzled offsets: 16B chunks XOR'ed by (row & 7)
__device__ __forceinline__ uint32_t off128(int r, int c) {   // 128 f16/row
    return (uint32_t)(r * 256) + ((((c >> 3) ^ (r & 7)) << 4) | ((c & 7) * 2));
}
__device__ __forceinline__ void cpa16(uint32_t dst, const void* src, int srcsize) {
    asm volatile("cp.async.cg.shared.global [%0], [%1], 16, %2;"
                 :: "r"(dst), "l"(src), "r"(srcsize) : "memory");
}
__device__ __forceinline__ void cpa_commit() { asm volatile("cp.async.commit_group;" ::: "memory"); }
__device__ __forceinline__ void cpa_wait0()  { asm volatile("cp.async.wait_group 0;"  ::: "memory"); }

__device__ __forceinline__ void ldm4(uint32_t& r0, uint32_t& r1, uint32_t& r2, uint32_t& r3, uint32_t a) {
    asm volatile("ldmatrix.sync.aligned.m8n8.x4.shared.b16 {%0,%1,%2,%3}, [%4];"
                 : "=r"(r0), "=r"(r1), "=r"(r2), "=r"(r3) : "r"(a));
}
__device__ __forceinline__ void ldm4t(uint32_t& r0, uint32_t& r1, uint32_t& r2, uint32_t& r3, uint32_t a) {
    asm volatile("ldmatrix.sync.aligned.m8n8.x4.trans.shared.b16 {%0,%1,%2,%3}, [%4];"
                 : "=r"(r0), "=r"(r1), "=r"(r2), "=r"(r3) : "r"(a));
}
// f32-accumulator MMA (GEMM2)
__device__ __forceinline__ void mma16816h(float* d, const uint32_t* a, const uint32_t* b) {
    asm volatile("mma.sync.aligned.m16n8k16.row.col.f32.f16.f16.f32 "
                 "{%0,%1,%2,%3}, {%4,%5,%6,%7}, {%8,%9}, {%0,%1,%2,%3};"
                 : "+f"(d[0]), "+f"(d[1]), "+f"(d[2]), "+f"(d[3])
                 : "r"(a[0]), "r"(a[1]), "r"(a[2]), "r"(a[3]), "r"(b[0]), "r"(b[1]));
}
// f16-accumulator MMA (GEMM1): D regs are f16x2 {c0,c1},{c2,c3}
__device__ __forceinline__ void mma16816hh(uint32_t* d, const uint32_t* a, const uint32_t* b) {
    asm volatile("mma.sync.aligned.m16n8k16.row.col.f16.f16.f16.f16 "
                 "{%0,%1}, {%2,%3,%4,%5}, {%6,%7}, {%0,%1};"
                 : "+r"(d[0]), "+r"(d[1])
                 : "r"(a[0]), "r"(a[1]), "r"(a[2]), "r"(a[3]), "r"(b[0]), "r"(b[1]));
}
__device__ __forceinline__ void red_add_v2(float* p, float a, float b) {
    asm volatile("red.global.add.v2.f32 [%0], {%1, %2};" :: "l"(p), "f"(a), "f"(b) : "memory");
}
__device__ __forceinline__ void red_add_v4(float* p, float a, float b, float c, float d) {
    asm volatile("red.global.add.v4.f32 [%0], {%1, %2, %3, %4};"
                 :: "l"(p), "f"(a), "f"(b), "f"(c), "f"(d) : "memory");
}
__device__ __forceinline__ uint32_t pack_h2(float a, float b) {
    uint32_t p;
    asm("cvt.rn.f16x2.f32 %0, %1, %2;" : "=r"(p) : "f"(b), "f"(a));
    return p;
}
__device__ __forceinline__ float2 unpack_h2(uint32_t p) {
    __half2 h = *reinterpret_cast<__half2*>(&p);
    return __half22float2(h);
}

// ---------------------------------------------------------------------------
__global__ void init_kernel(const float* __restrict__ x, float* __restrict__ out) {
    int i = blockIdx.x * blockDim.x + threadIdx.x;
    if (i < N_NODES * DD) { g_aggr[i] = 0.1f * x[i]; out[i] = 0.0f; }
}

__global__ void scatter_kernel(const float* __restrict__ x, const int* __restrict__ eidx,
                               const int* __restrict__ rid, const int* __restrict__ neg,
                               const float* __restrict__ rel) {
    int gw = (blockIdx.x * blockDim.x + threadIdx.x) >> 5;
    int lane = threadIdx.x & 31;
    if (gw >= N_EDGES) return;
    int src = eidx[gw], dst = eidx[N_EDGES + gw], r = rid[gw];
    float coef = 1.0f - 2.0f * (float)neg[gw];
    float4 xv = ((const float4*)(x + (size_t)src * DD))[lane];
    float4 rv = ((const float4*)(rel + (size_t)r * DD))[lane];
    red_add_v4(g_aggr + (size_t)dst * DD + lane * 4,
               (xv.x + rv.x) * coef, (xv.y + rv.y) * coef,
               (xv.z + rv.z) * coef, (xv.w + rv.w) * coef);
}

__global__ void prep_kernel(const float* __restrict__ eemb) {
    int i = blockIdx.x * blockDim.x + threadIdx.x;    // over N_ENT*64 float2
    if (i >= N_ENT * (DD / 2)) return;
    float2 v = ((const float2*)eemb)[i];
    ((uint32_t*)g_Eh)[i] = pack_h2(v.x, v.y);
}

// ---------------------------------------------------------------------------
__global__ void __launch_bounds__(NTHR, 2)
gemm_fused(const float* __restrict__ scal, const float* __restrict__ bias,
           float* __restrict__ out) {
    extern __shared__ char smem[];
    const uint32_t sb = s2u(smem);
    const int tid = threadIdx.x, wid = tid >> 5, lane = tid & 31;
    const int mt = blockIdx.x & (MTILES - 1), sp = blockIdx.x / MTILES;
    const int m0 = mt * BM;
    const int t0 = sp * TPS, t1 = min(NVT, t0 + TPS);
    if (t0 >= t1) return;

    const int wm = wid * 32;               // warp owns rows [wm, wm+32): 2 m16

    auto load_tiles = [&](int t, int b) {
        const int v0 = t * BV;
        const uint32_t eb = sb + SM_EB + b * EB_STRIDE;
        for (int i = tid; i < 1024; i += NTHR) {    // E [64v,128d] fp16, 16B chunks
            int v = i >> 4, dg = (i & 15) * 8;
            int gv = v0 + v;
            uint32_t o = off128(v, dg);
            int sz = (gv < N_ENT) ? 16 : 0;
            const void* pE = sz ? (const void*)(g_Eh + (size_t)gv * DD + dg) : (const void*)g_Eh;
            cpa16(eb + EB_E + o, pE, sz);
        }
        if (tid < 32) {                              // 64 scale + 64 bias f32
            int half = tid >> 4, g = tid & 15;
            int gv = v0 + g * 4;
            int rem = N_ENT - gv;
            int sz = rem >= 4 ? 16 : (rem > 0 ? rem * 4 : 0);
            const float* src = half ? bias : scal;
            const void* p = sz ? (const void*)(src + gv) : (const void*)src;
            cpa16(eb + EB_SCB + half * 256 + g * 16, p, sz);
        }
    };

    // issue tile-0 E loads first so they overlap the A staging below
    load_tiles(t0, 0);
    cpa_commit();

    // ---- A tile: g_aggr f32 -> fp16, swizzled (staged once) ----
    for (int i = tid; i < BM * (DD / 4); i += NTHR) {
        int m = i >> 5, k = (i & 31) * 4;
        float4 a = *(const float4*)(g_aggr + (size_t)(m0 + m) * DD + k);
        *(uint32_t*)(smem + SM_A + off128(m, k))     = pack_h2(a.x, a.y);
        *(uint32_t*)(smem + SM_A + off128(m, k + 2)) = pack_h2(a.z, a.w);
    }
    __syncthreads();

    // per-lane ldmatrix pieces (constant across loop)
    const int lr16 = lane & 15;            // row within 16
    const int lc8  = (lane >> 4) << 3;     // +8 col for upper half-warp
    const int lrB  = (lane & 7) | ((lane & 16) >> 1);  // B non-trans row
    const int lcB  = lane & 8;                          // B non-trans col sel
    const int ce   = (lane & 3) * 2;       // C/epilogue col pair base

    float accO[2][16][4];                   // 2 m16 x 128d per warp
    #pragma unroll
    for (int mi = 0; mi < 2; mi++)
        #pragma unroll
        for (int nt = 0; nt < 16; nt++)
            #pragma unroll
            for (int q = 0; q < 4; q++) accO[mi][nt][q] = 0.0f;

    for (int t = t0; t < t1; ++t) {
        const int buf = (t - t0) & 1;
        const uint32_t eb = sb + SM_EB + buf * EB_STRIDE;

        cpa_wait0();           // tile t landed (this thread's copies)
        __syncthreads();       // visible to all; all warps done with buf^1
        if (t + 1 < t1) { load_tiles(t + 1, buf ^ 1); cpa_commit(); }

        // -------- GEMM1: S[32m x 64v] per warp, fp16 accumulators -----------
        uint32_t accS[2][8][2];             // f16x2 D frags
        #pragma unroll
        for (int mi = 0; mi < 2; mi++)
            #pragma unroll
            for (int nt = 0; nt < 8; nt++)
                accS[mi][nt][0] = accS[mi][nt][1] = 0u;

        #pragma unroll
        for (int ks = 0; ks < 8; ks++) {
            const int k0 = ks * 16;
            uint32_t aA[2][4];
            #pragma unroll
            for (int mi = 0; mi < 2; mi++) {
                uint32_t o = off128(wm + mi * 16 + lr16, k0 + lc8);
                ldm4(aA[mi][0], aA[mi][1], aA[mi][2], aA[mi][3], sb + SM_A + o);
            }
            uint32_t bF[8][2];
            #pragma unroll
            for (int ng = 0; ng < 4; ng++) {
                uint32_t o = off128(ng * 16 + lrB, k0 + lcB);
                uint32_t r0, r1, r2, r3;
                ldm4(r0, r1, r2, r3, eb + EB_E + o);
                bF[ng * 2][0] = r0; bF[ng * 2][1] = r1;
                bF[ng * 2 + 1][0] = r2; bF[ng * 2 + 1][1] = r3;
            }
            #pragma unroll
            for (int mi = 0; mi < 2; mi++)
                #pragma unroll
                for (int nt = 0; nt < 8; nt++)
                    mma16816hh(accS[mi][nt], aA[mi], bF[nt]);
        }

        // ------- epilogue in registers: relu(scale*s+bias) -> GEMM2 A frags --
        // f16 D frag {c0,c1},{c2,c3}; C->A identity as before.
        uint32_t aS[2][4][4];
        {
            const float* scb = (const float*)(smem + SM_EB + buf * EB_STRIDE + EB_SCB);
            #pragma unroll
            for (int nt = 0; nt < 8; nt++) {
                const int c = nt * 8 + ce;
                float2 scv = *(const float2*)(scb + c);
                float2 biv = *(const float2*)(scb + 64 + c);
                #pragma unroll
                for (int mi = 0; mi < 2; mi++) {
                    float2 s0 = unpack_h2(accS[mi][nt][0]);
                    float2 s1 = unpack_h2(accS[mi][nt][1]);
                    float v00 = fmaxf(fmaf(s0.x, scv.x, biv.x), 0.f);
                    float v01 = fmaxf(fmaf(s0.y, scv.y, biv.y), 0.f);
                    float v10 = fmaxf(fmaf(s1.x, scv.x, biv.x), 0.f);
                    float v11 = fmaxf(fmaf(s1.y, scv.y, biv.y), 0.f);
                    const int g = nt >> 1, sub = (nt & 1) * 2;
                    aS[mi][g][sub]     = pack_h2(v00, v01);
                    aS[mi][g][sub + 1] = pack_h2(v10, v11);
                }
            }
        }

        // ---------------- GEMM2: O[32m x 128d] += S' . E ---------------------
        #pragma unroll
        for (int g = 0; g < 4; g++) {          // k16 groups over v
            const int k0 = g * 16;
            #pragma unroll
            for (int half = 0; half < 2; half++) {
                uint32_t bF[8][2];
                #pragma unroll
                for (int ng = 0; ng < 4; ng++) {
                    uint32_t o = off128(k0 + lr16, half * 64 + ng * 16 + lc8);
                    uint32_t r0, r1, r2, r3;
                    ldm4t(r0, r1, r2, r3, eb + EB_E + o);
                    bF[ng * 2][0] = r0; bF[ng * 2][1] = r1;
                    bF[ng * 2 + 1][0] = r2; bF[ng * 2 + 1][1] = r3;
                }
                #pragma unroll
                for (int mi = 0; mi < 2; mi++)
                    #pragma unroll
                    for (int ng = 0; ng < 8; ng++)
                        mma16816h(accO[mi][half * 8 + ng], aS[mi][g], bF[ng]);
            }
        }
    }

    // ---- flush O to out (+= across splits) ----
    #pragma unroll
    for (int mi = 0; mi < 2; mi++) {
        const int r0 = m0 + wm + mi * 16 + (lane >> 2);
        #pragma unroll
        for (int nt = 0; nt < 16; nt++) {
            const int c = nt * 8 + ce;
            red_add_v2(out + (size_t)r0 * DD + c,       accO[mi][nt][0], accO[mi][nt][1]);
            red_add_v2(out + (size_t)(r0 + 8) * DD + c, accO[mi][nt][2], accO[mi][nt][3]);
        }
    }
}

// ---------------------------------------------------------------------------
extern "C" void kernel_launch(void* const* d_in, const int* in_sizes, int n_in,
                              void* d_out, int out_size) {
    const float* x     = (const float*)d_in[0];
    const int*   eidx  = (const int*)  d_in[1];
    const int*   rid   = (const int*)  d_in[2];
    const int*   neg   = (const int*)  d_in[3];
    const float* rel   = (const float*)d_in[4];
    const float* eemb  = (const float*)d_in[5];
    const float* scale = (const float*)d_in[6];
    const float* bias  = (const float*)d_in[7];
    float* out = (float*)d_out;

    cudaFuncSetAttribute(gemm_fused, cudaFuncAttributeMaxDynamicSharedMemorySize, SMEM_BYTES);

    prep_kernel<<<(N_ENT * (DD / 2) + 255) / 256, 256>>>(eemb);
    init_kernel<<<(N_NODES * DD + 255) / 256, 256>>>(x, out);
    scatter_kernel<<<N_EDGES * 32 / 256, 256>>>(x, eidx, rid, neg, rel);
    gemm_fused<<<MTILES * NSPLIT, NTHR, SMEM_BYTES>>>(scale, bias, out);
}

// round 12
// speedup vs baseline: 12.3763x; 1.0040x over previous
#include <cuda_runtime.h>
#include <cuda_fp16.h>
#include <cstdint>

// ---------------------------------------------------------------------------
// LMPNN round 12: R11 + (a) per-g epilogue/GEMM2 interleave (aS live range
// 32->8 regs, un-cap registers), (b) fp16 gather in scatter (x/rel converted
// in prep; halves scatter L2 read traffic; atomics stay f32).
// ---------------------------------------------------------------------------

#define DD 128
static constexpr int N_NODES = 4096;
static constexpr int N_EDGES = 262144;
static constexpr int N_ENT   = 50000;
static constexpr int N_REL   = 1000;

static constexpr int BM = 128;
static constexpr int BV = 64;
static constexpr int NVT = (N_ENT + BV - 1) / BV;        // 782
static constexpr int NSPLIT = 9;
static constexpr int TPS = (NVT + NSPLIT - 1) / NSPLIT;  // 87
static constexpr int MTILES = N_NODES / BM;              // 32
static constexpr int NTHR = 128;                         // 4 warps x 32 rows

__device__ float  g_aggr[N_NODES * DD];
__device__ __half g_Eh[(size_t)N_ENT * DD];
__device__ __half g_xh[N_NODES * DD];
__device__ __half g_relh[N_REL * DD];

// ---- smem map (bytes) ------------------------------------------------------
static constexpr int SM_A  = 0;           // 32768  A [128m,128k] fp16
static constexpr int SM_EB = 32768;       // 2 bufs x 16896
static constexpr int EB_E   = 0;          // 16384  E [64v,128d] fp16
static constexpr int EB_SCB = 16384;      // 512 (64 scale f32 + 64 bias f32)
static constexpr int EB_STRIDE = 16896;
static constexpr int SMEM_BYTES = 32768 + 2 * EB_STRIDE;  // 66560; x2/SM ok

// ---------------------------------------------------------------------------
__device__ __forceinline__ uint32_t s2u(const void* p) {
    uint32_t a;
    asm("{ .reg .u64 t; cvta.to.shared.u64 t, %1; cvt.u32.u64 %0, t; }" : "=r"(a) : "l"(p));
    return a;
}
// swizzled offsets: 16B chunks XOR'ed by (row & 7)
__device__ __forceinline__ uint32_t off128(int r, int c) {   // 128 f16/row
    return (uint32_t)(r * 256) + ((((c >> 3) ^ (r & 7)) << 4) | ((c & 7) * 2));
}
__device__ __forceinline__ void cpa16(uint32_t dst, const void* src, int srcsize) {
    asm volatile("cp.async.cg.shared.global [%0], [%1], 16, %2;"
                 :: "r"(dst), "l"(src), "r"(srcsize) : "memory");
}
__device__ __forceinline__ void cpa_commit() { asm volatile("cp.async.commit_group;" ::: "memory"); }
__device__ __forceinline__ void cpa_wait0()  { asm volatile("cp.async.wait_group 0;"  ::: "memory"); }

__device__ __forceinline__ void ldm4(uint32_t& r0, uint32_t& r1, uint32_t& r2, uint32_t& r3, uint32_t a) {
    asm volatile("ldmatrix.sync.aligned.m8n8.x4.shared.b16 {%0,%1,%2,%3}, [%4];"
                 : "=r"(r0), "=r"(r1), "=r"(r2), "=r"(r3) : "r"(a));
}
__device__ __forceinline__ void ldm4t(uint32_t& r0, uint32_t& r1, uint32_t& r2, uint32_t& r3, uint32_t a) {
    asm volatile("ldmatrix.sync.aligned.m8n8.x4.trans.shared.b16 {%0,%1,%2,%3}, [%4];"
                 : "=r"(r0), "=r"(r1), "=r"(r2), "=r"(r3) : "r"(a));
}
// f32-accumulator MMA (GEMM2)
__device__ __forceinline__ void mma16816h(float* d, const uint32_t* a, const uint32_t* b) {
    asm volatile("mma.sync.aligned.m16n8k16.row.col.f32.f16.f16.f32 "
                 "{%0,%1,%2,%3}, {%4,%5,%6,%7}, {%8,%9}, {%0,%1,%2,%3};"
                 : "+f"(d[0]), "+f"(d[1]), "+f"(d[2]), "+f"(d[3])
                 : "r"(a[0]), "r"(a[1]), "r"(a[2]), "r"(a[3]), "r"(b[0]), "r"(b[1]));
}
// f16-accumulator MMA (GEMM1): D regs are f16x2 {c0,c1},{c2,c3}
__device__ __forceinline__ void mma16816hh(uint32_t* d, const uint32_t* a, const uint32_t* b) {
    asm volatile("mma.sync.aligned.m16n8k16.row.col.f16.f16.f16.f16 "
                 "{%0,%1}, {%2,%3,%4,%5}, {%6,%7}, {%0,%1};"
                 : "+r"(d[0]), "+r"(d[1])
                 : "r"(a[0]), "r"(a[1]), "r"(a[2]), "r"(a[3]), "r"(b[0]), "r"(b[1]));
}
__device__ __forceinline__ void red_add_v2(float* p, float a, float b) {
    asm volatile("red.global.add.v2.f32 [%0], {%1, %2};" :: "l"(p), "f"(a), "f"(b) : "memory");
}
__device__ __forceinline__ void red_add_v4(float* p, float a, float b, float c, float d) {
    asm volatile("red.global.add.v4.f32 [%0], {%1, %2, %3, %4};"
                 :: "l"(p), "f"(a), "f"(b), "f"(c), "f"(d) : "memory");
}
__device__ __forceinline__ uint32_t pack_h2(float a, float b) {
    uint32_t p;
    asm("cvt.rn.f16x2.f32 %0, %1, %2;" : "=r"(p) : "f"(b), "f"(a));
    return p;
}
__device__ __forceinline__ float2 unpack_h2(uint32_t p) {
    __half2 h = *reinterpret_cast<__half2*>(&p);
    return __half22float2(h);
}

// ---------------------------------------------------------------------------
__global__ void init_kernel(const float* __restrict__ x, float* __restrict__ out) {
    int i = blockIdx.x * blockDim.x + threadIdx.x;
    if (i < N_NODES * DD) { g_aggr[i] = 0.1f * x[i]; out[i] = 0.0f; }
}

// prep: convert E, x, rel to fp16 (one pass, disjoint index ranges)
static constexpr int PREP_E = N_ENT * (DD / 2);          // f2 units
static constexpr int PREP_X = N_NODES * (DD / 2);
static constexpr int PREP_R = N_REL * (DD / 2);
static constexpr int PREP_TOT = PREP_E + PREP_X + PREP_R;

__global__ void prep_kernel(const float* __restrict__ eemb,
                            const float* __restrict__ x,
                            const float* __restrict__ rel) {
    int i = blockIdx.x * blockDim.x + threadIdx.x;
    if (i >= PREP_TOT) return;
    if (i < PREP_E) {
        float2 v = ((const float2*)eemb)[i];
        ((uint32_t*)g_Eh)[i] = pack_h2(v.x, v.y);
    } else if (i < PREP_E + PREP_X) {
        int j = i - PREP_E;
        float2 v = ((const float2*)x)[j];
        ((uint32_t*)g_xh)[j] = pack_h2(v.x, v.y);
    } else {
        int j = i - PREP_E - PREP_X;
        float2 v = ((const float2*)rel)[j];
        ((uint32_t*)g_relh)[j] = pack_h2(v.x, v.y);
    }
}

__global__ void scatter_kernel(const int* __restrict__ eidx,
                               const int* __restrict__ rid, const int* __restrict__ neg) {
    int gw = (blockIdx.x * blockDim.x + threadIdx.x) >> 5;
    int lane = threadIdx.x & 31;
    if (gw >= N_EDGES) return;
    int src = eidx[gw], dst = eidx[N_EDGES + gw], r = rid[gw];
    float coef = 1.0f - 2.0f * (float)neg[gw];
    uint2 xv = ((const uint2*)(g_xh   + (size_t)src * DD))[lane];
    uint2 rv = ((const uint2*)(g_relh + (size_t)r   * DD))[lane];
    float2 x01 = unpack_h2(xv.x), x23 = unpack_h2(xv.y);
    float2 r01 = unpack_h2(rv.x), r23 = unpack_h2(rv.y);
    red_add_v4(g_aggr + (size_t)dst * DD + lane * 4,
               (x01.x + r01.x) * coef, (x01.y + r01.y) * coef,
               (x23.x + r23.x) * coef, (x23.y + r23.y) * coef);
}

// ---------------------------------------------------------------------------
__global__ void __launch_bounds__(NTHR, 2)
gemm_fused(const float* __restrict__ scal, const float* __restrict__ bias,
           float* __restrict__ out) {
    extern __shared__ char smem[];
    const uint32_t sb = s2u(smem);
    const int tid = threadIdx.x, wid = tid >> 5, lane = tid & 31;
    const int mt = blockIdx.x & (MTILES - 1), sp = blockIdx.x / MTILES;
    const int m0 = mt * BM;
    const int t0 = sp * TPS, t1 = min(NVT, t0 + TPS);
    if (t0 >= t1) return;

    const int wm = wid * 32;               // warp owns rows [wm, wm+32): 2 m16

    auto load_tiles = [&](int t, int b) {
        const int v0 = t * BV;
        const uint32_t eb = sb + SM_EB + b * EB_STRIDE;
        for (int i = tid; i < 1024; i += NTHR) {    // E [64v,128d] fp16, 16B chunks
            int v = i >> 4, dg = (i & 15) * 8;
            int gv = v0 + v;
            uint32_t o = off128(v, dg);
            int sz = (gv < N_ENT) ? 16 : 0;
            const void* pE = sz ? (const void*)(g_Eh + (size_t)gv * DD + dg) : (const void*)g_Eh;
            cpa16(eb + EB_E + o, pE, sz);
        }
        if (tid < 32) {                              // 64 scale + 64 bias f32
            int half = tid >> 4, g = tid & 15;
            int gv = v0 + g * 4;
            int rem = N_ENT - gv;
            int sz = rem >= 4 ? 16 : (rem > 0 ? rem * 4 : 0);
            const float* src = half ? bias : scal;
            const void* p = sz ? (const void*)(src + gv) : (const void*)src;
            cpa16(eb + EB_SCB + half * 256 + g * 16, p, sz);
        }
    };

    // issue tile-0 E loads first so they overlap the A staging below
    load_tiles(t0, 0);
    cpa_commit();

    // ---- A tile: g_aggr f32 -> fp16, swizzled (staged once) ----
    for (int i = tid; i < BM * (DD / 4); i += NTHR) {
        int m = i >> 5, k = (i & 31) * 4;
        float4 a = *(const float4*)(g_aggr + (size_t)(m0 + m) * DD + k);
        *(uint32_t*)(smem + SM_A + off128(m, k))     = pack_h2(a.x, a.y);
        *(uint32_t*)(smem + SM_A + off128(m, k + 2)) = pack_h2(a.z, a.w);
    }
    __syncthreads();

    // per-lane ldmatrix pieces (constant across loop)
    const int lr16 = lane & 15;            // row within 16
    const int lc8  = (lane >> 4) << 3;     // +8 col for upper half-warp
    const int lrB  = (lane & 7) | ((lane & 16) >> 1);  // B non-trans row
    const int lcB  = lane & 8;                          // B non-trans col sel
    const int ce   = (lane & 3) * 2;       // C/epilogue col pair base

    float accO[2][16][4];                   // 2 m16 x 128d per warp
    #pragma unroll
    for (int mi = 0; mi < 2; mi++)
        #pragma unroll
        for (int nt = 0; nt < 16; nt++)
            #pragma unroll
            for (int q = 0; q < 4; q++) accO[mi][nt][q] = 0.0f;

    for (int t = t0; t < t1; ++t) {
        const int buf = (t - t0) & 1;
        const uint32_t eb = sb + SM_EB + buf * EB_STRIDE;

        cpa_wait0();           // tile t landed (this thread's copies)
        __syncthreads();       // visible to all; all warps done with buf^1
        if (t + 1 < t1) { load_tiles(t + 1, buf ^ 1); cpa_commit(); }

        // -------- GEMM1: S[32m x 64v] per warp, fp16 accumulators -----------
        uint32_t accS[2][8][2];             // f16x2 D frags
        #pragma unroll
        for (int mi = 0; mi < 2; mi++)
            #pragma unroll
            for (int nt = 0; nt < 8; nt++)
                accS[mi][nt][0] = accS[mi][nt][1] = 0u;

        #pragma unroll
        for (int ks = 0; ks < 8; ks++) {
            const int k0 = ks * 16;
            uint32_t aA[2][4];
            #pragma unroll
            for (int mi = 0; mi < 2; mi++) {
                uint32_t o = off128(wm + mi * 16 + lr16, k0 + lc8);
                ldm4(aA[mi][0], aA[mi][1], aA[mi][2], aA[mi][3], sb + SM_A + o);
            }
            uint32_t bF[8][2];
            #pragma unroll
            for (int ng = 0; ng < 4; ng++) {
                uint32_t o = off128(ng * 16 + lrB, k0 + lcB);
                uint32_t r0, r1, r2, r3;
                ldm4(r0, r1, r2, r3, eb + EB_E + o);
                bF[ng * 2][0] = r0; bF[ng * 2][1] = r1;
                bF[ng * 2 + 1][0] = r2; bF[ng * 2 + 1][1] = r3;
            }
            #pragma unroll
            for (int mi = 0; mi < 2; mi++)
                #pragma unroll
                for (int nt = 0; nt < 8; nt++)
                    mma16816hh(accS[mi][nt], aA[mi], bF[nt]);
        }

        // ---- per-g: epilogue (registers) -> GEMM2 for that k16 group -------
        // f16 D frag {c0,c1},{c2,c3}; C->A identity within group g = nt>>1.
        const float* scb = (const float*)(smem + SM_EB + buf * EB_STRIDE + EB_SCB);
        #pragma unroll
        for (int g = 0; g < 4; g++) {
            uint32_t aS[2][4];
            #pragma unroll
            for (int sub2 = 0; sub2 < 2; sub2++) {      // nt = 2g, 2g+1
                const int nt = 2 * g + sub2;
                const int c = nt * 8 + ce;
                float2 scv = *(const float2*)(scb + c);
                float2 biv = *(const float2*)(scb + 64 + c);
                #pragma unroll
                for (int mi = 0; mi < 2; mi++) {
                    float2 s0 = unpack_h2(accS[mi][nt][0]);
                    float2 s1 = unpack_h2(accS[mi][nt][1]);
                    float v00 = fmaxf(fmaf(s0.x, scv.x, biv.x), 0.f);
                    float v01 = fmaxf(fmaf(s0.y, scv.y, biv.y), 0.f);
                    float v10 = fmaxf(fmaf(s1.x, scv.x, biv.x), 0.f);
                    float v11 = fmaxf(fmaf(s1.y, scv.y, biv.y), 0.f);
                    aS[mi][sub2 * 2]     = pack_h2(v00, v01);
                    aS[mi][sub2 * 2 + 1] = pack_h2(v10, v11);
                }
            }
            const int k0 = g * 16;
            #pragma unroll
            for (int half = 0; half < 2; half++) {
                uint32_t bF[8][2];
                #pragma unroll
                for (int ng = 0; ng < 4; ng++) {
                    uint32_t o = off128(k0 + lr16, half * 64 + ng * 16 + lc8);
                    uint32_t r0, r1, r2, r3;
                    ldm4t(r0, r1, r2, r3, eb + EB_E + o);
                    bF[ng * 2][0] = r0; bF[ng * 2][1] = r1;
                    bF[ng * 2 + 1][0] = r2; bF[ng * 2 + 1][1] = r3;
                }
                #pragma unroll
                for (int mi = 0; mi < 2; mi++)
                    #pragma unroll
                    for (int ng = 0; ng < 8; ng++)
                        mma16816h(accO[mi][half * 8 + ng], aS[mi], bF[ng]);
            }
        }
    }

    // ---- flush O to out (+= across splits) ----
    #pragma unroll
    for (int mi = 0; mi < 2; mi++) {
        const int r0 = m0 + wm + mi * 16 + (lane >> 2);
        #pragma unroll
        for (int nt = 0; nt < 16; nt++) {
            const int c = nt * 8 + ce;
            red_add_v2(out + (size_t)r0 * DD + c,       accO[mi][nt][0], accO[mi][nt][1]);
            red_add_v2(out + (size_t)(r0 + 8) * DD + c, accO[mi][nt][2], accO[mi][nt][3]);
        }
    }
}

// ---------------------------------------------------------------------------
extern "C" void kernel_launch(void* const* d_in, const int* in_sizes, int n_in,
                              void* d_out, int out_size) {
    const float* x     = (const float*)d_in[0];
    const int*   eidx  = (const int*)  d_in[1];
    const int*   rid   = (const int*)  d_in[2];
    const int*   neg   = (const int*)  d_in[3];
    const float* rel   = (const float*)d_in[4];
    const float* eemb  = (const float*)d_in[5];
    const float* scale = (const float*)d_in[6];
    const float* bias  = (const float*)d_in[7];
    float* out = (float*)d_out;

    cudaFuncSetAttribute(gemm_fused, cudaFuncAttributeMaxDynamicSharedMemorySize, SMEM_BYTES);

    prep_kernel<<<(PREP_TOT + 255) / 256, 256>>>(eemb, x, rel);
    init_kernel<<<(N_NODES * DD + 255) / 256, 256>>>(x, out);
    scatter_kernel<<<N_EDGES * 32 / 256, 256>>>(eidx, rid, neg);
    gemm_fused<<<MTILES * NSPLIT, NTHR, SMEM_BYTES>>>(scale, bias, out);
}

// round 13
// speedup vs baseline: 12.8170x; 1.0356x over previous
#include <cuda_runtime.h>
#include <cuda_fp16.h>
#include <cstdint>

// ---------------------------------------------------------------------------
// LMPNN round 13: R12 + (a) fully-packed f16x2 epilogue (scale/bias pre-
// converted to f16; D-frag == A-frag, zero repack), (b) init fused into prepA,
// (c) E/scale/bias conversion merged into the scatter kernel as extra blocks.
// ---------------------------------------------------------------------------

#define DD 128
static constexpr int N_NODES = 4096;
static constexpr int N_EDGES = 262144;
static constexpr int N_ENT   = 50000;
static constexpr int N_REL   = 1000;

static constexpr int BM = 128;
static constexpr int BV = 64;
static constexpr int NVT = (N_ENT + BV - 1) / BV;        // 782
static constexpr int NSPLIT = 9;
static constexpr int TPS = (NVT + NSPLIT - 1) / NSPLIT;  // 87
static constexpr int MTILES = N_NODES / BM;              // 32
static constexpr int NTHR = 128;                         // 4 warps x 32 rows

__device__ float  g_aggr[N_NODES * DD];
__device__ __half g_Eh[(size_t)N_ENT * DD];
__device__ __half g_xh[N_NODES * DD];
__device__ __half g_relh[N_REL * DD];
__device__ __half g_sch[N_ENT];
__device__ __half g_bih[N_ENT];

// ---- smem map (bytes) ------------------------------------------------------
static constexpr int SM_A  = 0;           // 32768  A [128m,128k] fp16
static constexpr int SM_EB = 32768;       // 2 bufs x 16640
static constexpr int EB_E   = 0;          // 16384  E [64v,128d] fp16
static constexpr int EB_SCB = 16384;      // 256 (64 sc f16 + 64 bi f16)
static constexpr int EB_STRIDE = 16640;
static constexpr int SMEM_BYTES = 32768 + 2 * EB_STRIDE;  // 66048; x2/SM ok

// ---------------------------------------------------------------------------
__device__ __forceinline__ uint32_t s2u(const void* p) {
    uint32_t a;
    asm("{ .reg .u64 t; cvta.to.shared.u64 t, %1; cvt.u32.u64 %0, t; }" : "=r"(a) : "l"(p));
    return a;
}
// swizzled offsets: 16B chunks XOR'ed by (row & 7)
__device__ __forceinline__ uint32_t off128(int r, int c) {   // 128 f16/row
    return (uint32_t)(r * 256) + ((((c >> 3) ^ (r & 7)) << 4) | ((c & 7) * 2));
}
__device__ __forceinline__ void cpa16(uint32_t dst, const void* src, int srcsize) {
    asm volatile("cp.async.cg.shared.global [%0], [%1], 16, %2;"
                 :: "r"(dst), "l"(src), "r"(srcsize) : "memory");
}
__device__ __forceinline__ void cpa_commit() { asm volatile("cp.async.commit_group;" ::: "memory"); }
__device__ __forceinline__ void cpa_wait0()  { asm volatile("cp.async.wait_group 0;"  ::: "memory"); }

__device__ __forceinline__ void ldm4(uint32_t& r0, uint32_t& r1, uint32_t& r2, uint32_t& r3, uint32_t a) {
    asm volatile("ldmatrix.sync.aligned.m8n8.x4.shared.b16 {%0,%1,%2,%3}, [%4];"
                 : "=r"(r0), "=r"(r1), "=r"(r2), "=r"(r3) : "r"(a));
}
__device__ __forceinline__ void ldm4t(uint32_t& r0, uint32_t& r1, uint32_t& r2, uint32_t& r3, uint32_t a) {
    asm volatile("ldmatrix.sync.aligned.m8n8.x4.trans.shared.b16 {%0,%1,%2,%3}, [%4];"
                 : "=r"(r0), "=r"(r1), "=r"(r2), "=r"(r3) : "r"(a));
}
// f32-accumulator MMA (GEMM2)
__device__ __forceinline__ void mma16816h(float* d, const uint32_t* a, const uint32_t* b) {
    asm volatile("mma.sync.aligned.m16n8k16.row.col.f32.f16.f16.f32 "
                 "{%0,%1,%2,%3}, {%4,%5,%6,%7}, {%8,%9}, {%0,%1,%2,%3};"
                 : "+f"(d[0]), "+f"(d[1]), "+f"(d[2]), "+f"(d[3])
                 : "r"(a[0]), "r"(a[1]), "r"(a[2]), "r"(a[3]), "r"(b[0]), "r"(b[1]));
}
// f16-accumulator MMA (GEMM1): D regs are f16x2 {c0,c1},{c2,c3}
__device__ __forceinline__ void mma16816hh(uint32_t* d, const uint32_t* a, const uint32_t* b) {
    asm volatile("mma.sync.aligned.m16n8k16.row.col.f16.f16.f16.f16 "
                 "{%0,%1}, {%2,%3,%4,%5}, {%6,%7}, {%0,%1};"
                 : "+r"(d[0]), "+r"(d[1])
                 : "r"(a[0]), "r"(a[1]), "r"(a[2]), "r"(a[3]), "r"(b[0]), "r"(b[1]));
}
__device__ __forceinline__ void red_add_v2(float* p, float a, float b) {
    asm volatile("red.global.add.v2.f32 [%0], {%1, %2};" :: "l"(p), "f"(a), "f"(b) : "memory");
}
__device__ __forceinline__ void red_add_v4(float* p, float a, float b, float c, float d) {
    asm volatile("red.global.add.v4.f32 [%0], {%1, %2, %3, %4};"
                 :: "l"(p), "f"(a), "f"(b), "f"(c), "f"(d) : "memory");
}
__device__ __forceinline__ uint32_t pack_h2(float a, float b) {
    uint32_t p;
    asm("cvt.rn.f16x2.f32 %0, %1, %2;" : "=r"(p) : "f"(b), "f"(a));
    return p;
}
__device__ __forceinline__ float2 unpack_h2(uint32_t p) {
    __half2 h = *reinterpret_cast<__half2*>(&p);
    return __half22float2(h);
}
__device__ __forceinline__ uint32_t hfma2_relu(uint32_t s, uint32_t sc, uint32_t bi) {
    uint32_t d;
    asm("fma.rn.f16x2 %0, %1, %2, %3;" : "=r"(d) : "r"(s), "r"(sc), "r"(bi));
    asm("max.f16x2 %0, %0, %1;" : "+r"(d) : "r"(0u));
    return d;
}

// ---------------------------------------------------------------------------
// prepA: x/rel -> fp16, g_aggr = 0.1x, out = 0
static constexpr int PA_X = N_NODES * (DD / 2);   // 262144 f2 units
static constexpr int PA_R = N_REL * (DD / 2);     // 64000

__global__ void prepA_kernel(const float* __restrict__ x,
                             const float* __restrict__ rel,
                             float* __restrict__ out) {
    int i = blockIdx.x * blockDim.x + threadIdx.x;
    if (i >= PA_X) return;
    float2 v = ((const float2*)x)[i];
    ((uint32_t*)g_xh)[i] = pack_h2(v.x, v.y);
    ((float2*)g_aggr)[i] = make_float2(0.1f * v.x, 0.1f * v.y);
    ((float2*)out)[i] = make_float2(0.f, 0.f);
    if (i < PA_R) {
        float2 r = ((const float2*)rel)[i];
        ((uint32_t*)g_relh)[i] = pack_h2(r.x, r.y);
    }
}

// combo: scatter (blocks [0, SCAT_BLK)) + E/scale/bias fp16 convert (rest)
static constexpr int SCAT_BLK = N_EDGES * 32 / 256;   // 32768
static constexpr int CV_E  = N_ENT * (DD / 2);        // 3,200,000 u32 items
static constexpr int CV_SC = N_ENT / 2;               // 25,000
static constexpr int CV_TOT = CV_E + 2 * CV_SC;       // 3,250,000
static constexpr int CV_BLK = (CV_TOT + 255) / 256;   // 12696

__global__ void combo_kernel(const int* __restrict__ eidx,
                             const int* __restrict__ rid, const int* __restrict__ neg,
                             const float* __restrict__ eemb,
                             const float* __restrict__ scal,
                             const float* __restrict__ bias) {
    if (blockIdx.x < SCAT_BLK) {
        int gw = (blockIdx.x * blockDim.x + threadIdx.x) >> 5;
        int lane = threadIdx.x & 31;
        int src = eidx[gw], dst = eidx[N_EDGES + gw], r = rid[gw];
        float coef = 1.0f - 2.0f * (float)neg[gw];
        uint2 xv = ((const uint2*)(g_xh   + (size_t)src * DD))[lane];
        uint2 rv = ((const uint2*)(g_relh + (size_t)r   * DD))[lane];
        float2 x01 = unpack_h2(xv.x), x23 = unpack_h2(xv.y);
        float2 r01 = unpack_h2(rv.x), r23 = unpack_h2(rv.y);
        red_add_v4(g_aggr + (size_t)dst * DD + lane * 4,
                   (x01.x + r01.x) * coef, (x01.y + r01.y) * coef,
                   (x23.x + r23.x) * coef, (x23.y + r23.y) * coef);
    } else {
        int j = (blockIdx.x - SCAT_BLK) * 256 + threadIdx.x;
        if (j < CV_E) {
            float2 v = ((const float2*)eemb)[j];
            ((uint32_t*)g_Eh)[j] = pack_h2(v.x, v.y);
        } else if (j < CV_E + CV_SC) {
            int k = j - CV_E;
            float2 v = ((const float2*)scal)[k];
            ((uint32_t*)g_sch)[k] = pack_h2(v.x, v.y);
        } else if (j < CV_TOT) {
            int k = j - CV_E - CV_SC;
            float2 v = ((const float2*)bias)[k];
            ((uint32_t*)g_bih)[k] = pack_h2(v.x, v.y);
        }
    }
}

// ---------------------------------------------------------------------------
__global__ void __launch_bounds__(NTHR, 2)
gemm_fused(float* __restrict__ out) {
    extern __shared__ char smem[];
    const uint32_t sb = s2u(smem);
    const int tid = threadIdx.x, wid = tid >> 5, lane = tid & 31;
    const int mt = blockIdx.x & (MTILES - 1), sp = blockIdx.x / MTILES;
    const int m0 = mt * BM;
    const int t0 = sp * TPS, t1 = min(NVT, t0 + TPS);
    if (t0 >= t1) return;

    const int wm = wid * 32;               // warp owns rows [wm, wm+32): 2 m16

    auto load_tiles = [&](int t, int b) {
        const int v0 = t * BV;
        const uint32_t eb = sb + SM_EB + b * EB_STRIDE;
        for (int i = tid; i < 1024; i += NTHR) {    // E [64v,128d] fp16, 16B chunks
            int v = i >> 4, dg = (i & 15) * 8;
            int gv = v0 + v;
            uint32_t o = off128(v, dg);
            int sz = (gv < N_ENT) ? 16 : 0;
            const void* pE = sz ? (const void*)(g_Eh + (size_t)gv * DD + dg) : (const void*)g_Eh;
            cpa16(eb + EB_E + o, pE, sz);
        }
        if (tid < 16) {                              // 64 sc f16 + 64 bi f16
            int half = tid >> 3, g = tid & 7;        // 8 x 16B per array
            int gv = v0 + g * 8;
            int rem = N_ENT - gv;
            int sz = rem >= 8 ? 16 : (rem > 0 ? rem * 2 : 0);
            const __half* src = half ? g_bih : g_sch;
            const void* p = sz ? (const void*)(src + gv) : (const void*)src;
            cpa16(eb + EB_SCB + half * 128 + g * 16, p, sz);
        }
    };

    // issue tile-0 E loads first so they overlap the A staging below
    load_tiles(t0, 0);
    cpa_commit();

    // ---- A tile: g_aggr f32 -> fp16, swizzled (staged once) ----
    for (int i = tid; i < BM * (DD / 4); i += NTHR) {
        int m = i >> 5, k = (i & 31) * 4;
        float4 a = *(const float4*)(g_aggr + (size_t)(m0 + m) * DD + k);
        *(uint32_t*)(smem + SM_A + off128(m, k))     = pack_h2(a.x, a.y);
        *(uint32_t*)(smem + SM_A + off128(m, k + 2)) = pack_h2(a.z, a.w);
    }
    __syncthreads();

    // per-lane ldmatrix pieces (constant across loop)
    const int lr16 = lane & 15;            // row within 16
    const int lc8  = (lane >> 4) << 3;     // +8 col for upper half-warp
    const int lrB  = (lane & 7) | ((lane & 16) >> 1);  // B non-trans row
    const int lcB  = lane & 8;                          // B non-trans col sel
    const int ce   = (lane & 3) * 2;       // C/epilogue col pair base

    float accO[2][16][4];                   // 2 m16 x 128d per warp
    #pragma unroll
    for (int mi = 0; mi < 2; mi++)
        #pragma unroll
        for (int nt = 0; nt < 16; nt++)
            #pragma unroll
            for (int q = 0; q < 4; q++) accO[mi][nt][q] = 0.0f;

    for (int t = t0; t < t1; ++t) {
        const int buf = (t - t0) & 1;
        const uint32_t eb = sb + SM_EB + buf * EB_STRIDE;

        cpa_wait0();           // tile t landed (this thread's copies)
        __syncthreads();       // visible to all; all warps done with buf^1
        if (t + 1 < t1) { load_tiles(t + 1, buf ^ 1); cpa_commit(); }

        // -------- GEMM1: S[32m x 64v] per warp, fp16 accumulators -----------
        uint32_t accS[2][8][2];             // f16x2 D frags
        #pragma unroll
        for (int mi = 0; mi < 2; mi++)
            #pragma unroll
            for (int nt = 0; nt < 8; nt++)
                accS[mi][nt][0] = accS[mi][nt][1] = 0u;

        #pragma unroll
        for (int ks = 0; ks < 8; ks++) {
            const int k0 = ks * 16;
            uint32_t aA[2][4];
            #pragma unroll
            for (int mi = 0; mi < 2; mi++) {
                uint32_t o = off128(wm + mi * 16 + lr16, k0 + lc8);
                ldm4(aA[mi][0], aA[mi][1], aA[mi][2], aA[mi][3], sb + SM_A + o);
            }
            uint32_t bF[8][2];
            #pragma unroll
            for (int ng = 0; ng < 4; ng++) {
                uint32_t o = off128(ng * 16 + lrB, k0 + lcB);
                uint32_t r0, r1, r2, r3;
                ldm4(r0, r1, r2, r3, eb + EB_E + o);
                bF[ng * 2][0] = r0; bF[ng * 2][1] = r1;
                bF[ng * 2 + 1][0] = r2; bF[ng * 2 + 1][1] = r3;
            }
            #pragma unroll
            for (int mi = 0; mi < 2; mi++)
                #pragma unroll
                for (int nt = 0; nt < 8; nt++)
                    mma16816hh(accS[mi][nt], aA[mi], bF[nt]);
        }

        // ---- per-g: packed f16x2 epilogue -> GEMM2 for that k16 group ------
        // f16 D frag {c0,c1},{c2,c3} IS the packed A frag; relu(s*sc+bi) in
        // fp16x2 keeps it packed. aS[sub]=f(accS[..][0]), aS[sub+1]=f(accS[..][1]).
        const __half* sch = (const __half*)(smem + SM_EB + buf * EB_STRIDE + EB_SCB);
        #pragma unroll
        for (int g = 0; g < 4; g++) {
            uint32_t aS[2][4];
            #pragma unroll
            for (int sub2 = 0; sub2 < 2; sub2++) {      // nt = 2g, 2g+1
                const int nt = 2 * g + sub2;
                const int c = nt * 8 + ce;
                uint32_t sc2 = *(const uint32_t*)(sch + c);
                uint32_t bi2 = *(const uint32_t*)(sch + 64 + c);
                #pragma unroll
                for (int mi = 0; mi < 2; mi++) {
                    aS[mi][sub2 * 2]     = hfma2_relu(accS[mi][nt][0], sc2, bi2);
                    aS[mi][sub2 * 2 + 1] = hfma2_relu(accS[mi][nt][1], sc2, bi2);
                }
            }
            const int k0 = g * 16;
            #pragma unroll
            for (int half = 0; half < 2; half++) {
                uint32_t bF[8][2];
                #pragma unroll
                for (int ng = 0; ng < 4; ng++) {
                    uint32_t o = off128(k0 + lr16, half * 64 + ng * 16 + lc8);
                    uint32_t r0, r1, r2, r3;
                    ldm4t(r0, r1, r2, r3, eb + EB_E + o);
                    bF[ng * 2][0] = r0; bF[ng * 2][1] = r1;
                    bF[ng * 2 + 1][0] = r2; bF[ng * 2 + 1][1] = r3;
                }
                #pragma unroll
                for (int mi = 0; mi < 2; mi++)
                    #pragma unroll
                    for (int ng = 0; ng < 8; ng++)
                        mma16816h(accO[mi][half * 8 + ng], aS[mi], bF[ng]);
            }
        }
    }

    // ---- flush O to out (+= across splits) ----
    #pragma unroll
    for (int mi = 0; mi < 2; mi++) {
        const int r0 = m0 + wm + mi * 16 + (lane >> 2);
        #pragma unroll
        for (int nt = 0; nt < 16; nt++) {
            const int c = nt * 8 + ce;
            red_add_v2(out + (size_t)r0 * DD + c,       accO[mi][nt][0], accO[mi][nt][1]);
            red_add_v2(out + (size_t)(r0 + 8) * DD + c, accO[mi][nt][2], accO[mi][nt][3]);
        }
    }
}

// ---------------------------------------------------------------------------
extern "C" void kernel_launch(void* const* d_in, const int* in_sizes, int n_in,
                              void* d_out, int out_size) {
    const float* x     = (const float*)d_in[0];
    const int*   eidx  = (const int*)  d_in[1];
    const int*   rid   = (const int*)  d_in[2];
    const int*   neg   = (const int*)  d_in[3];
    const float* rel   = (const float*)d_in[4];
    const float* eemb  = (const float*)d_in[5];
    const float* scale = (const float*)d_in[6];
    const float* bias  = (const float*)d_in[7];
    float* out = (float*)d_out;

    cudaFuncSetAttribute(gemm_fused, cudaFuncAttributeMaxDynamicSharedMemorySize, SMEM_BYTES);

    prepA_kernel<<<(PA_X + 255) / 256, 256>>>(x, rel, out);
    combo_kernel<<<SCAT_BLK + CV_BLK, 256>>>(eidx, rid, neg, eemb, scale, bias);
    gemm_fused<<<MTILES * NSPLIT, NTHR, SMEM_BYTES>>>(out);
}

// round 14
// speedup vs baseline: 12.9848x; 1.0131x over previous
#include <cuda_runtime.h>
#include <cuda_fp16.h>
#include <cstdint>

// ---------------------------------------------------------------------------
// LMPNN round 14: R13 + BV=128 entity tiles: GEMM1 ldm4/MMA 0.375->0.3125,
// half the per-tile barrier/epilogue boundaries (87->44 tiles per split).
// ---------------------------------------------------------------------------

#define DD 128
static constexpr int N_NODES = 4096;
static constexpr int N_EDGES = 262144;
static constexpr int N_ENT   = 50000;
static constexpr int N_REL   = 1000;

static constexpr int BM = 128;
static constexpr int BV = 128;
static constexpr int NVT = (N_ENT + BV - 1) / BV;        // 391
static constexpr int NSPLIT = 9;
static constexpr int TPS = (NVT + NSPLIT - 1) / NSPLIT;  // 44
static constexpr int MTILES = N_NODES / BM;              // 32
static constexpr int NTHR = 128;                         // 4 warps x 32 rows

__device__ float  g_aggr[N_NODES * DD];
__device__ __half g_Eh[(size_t)N_ENT * DD];
__device__ __half g_xh[N_NODES * DD];
__device__ __half g_relh[N_REL * DD];
__device__ __half g_sch[N_ENT];
__device__ __half g_bih[N_ENT];

// ---- smem map (bytes) ------------------------------------------------------
static constexpr int SM_A  = 0;           // 32768  A [128m,128k] fp16
static constexpr int SM_EB = 32768;       // 2 bufs x 33280
static constexpr int EB_E   = 0;          // 32768  E [128v,128d] fp16
static constexpr int EB_SCB = 32768;      // 512 (128 sc f16 + 128 bi f16)
static constexpr int EB_STRIDE = 33280;
static constexpr int SMEM_BYTES = 32768 + 2 * EB_STRIDE;  // 99328; x2/SM ok

// ---------------------------------------------------------------------------
__device__ __forceinline__ uint32_t s2u(const void* p) {
    uint32_t a;
    asm("{ .reg .u64 t; cvta.to.shared.u64 t, %1; cvt.u32.u64 %0, t; }" : "=r"(a) : "l"(p));
    return a;
}
// swizzled offsets: 16B chunks XOR'ed by (row & 7); rows of 128 f16 (256B)
__device__ __forceinline__ uint32_t off128(int r, int c) {
    return (uint32_t)(r * 256) + ((((c >> 3) ^ (r & 7)) << 4) | ((c & 7) * 2));
}
__device__ __forceinline__ void cpa16(uint32_t dst, const void* src, int srcsize) {
    asm volatile("cp.async.cg.shared.global [%0], [%1], 16, %2;"
                 :: "r"(dst), "l"(src), "r"(srcsize) : "memory");
}
__device__ __forceinline__ void cpa_commit() { asm volatile("cp.async.commit_group;" ::: "memory"); }
__device__ __forceinline__ void cpa_wait0()  { asm volatile("cp.async.wait_group 0;"  ::: "memory"); }

__device__ __forceinline__ void ldm4(uint32_t& r0, uint32_t& r1, uint32_t& r2, uint32_t& r3, uint32_t a) {
    asm volatile("ldmatrix.sync.aligned.m8n8.x4.shared.b16 {%0,%1,%2,%3}, [%4];"
                 : "=r"(r0), "=r"(r1), "=r"(r2), "=r"(r3) : "r"(a));
}
__device__ __forceinline__ void ldm4t(uint32_t& r0, uint32_t& r1, uint32_t& r2, uint32_t& r3, uint32_t a) {
    asm volatile("ldmatrix.sync.aligned.m8n8.x4.trans.shared.b16 {%0,%1,%2,%3}, [%4];"
                 : "=r"(r0), "=r"(r1), "=r"(r2), "=r"(r3) : "r"(a));
}
// f32-accumulator MMA (GEMM2)
__device__ __forceinline__ void mma16816h(float* d, const uint32_t* a, const uint32_t* b) {
    asm volatile("mma.sync.aligned.m16n8k16.row.col.f32.f16.f16.f32 "
                 "{%0,%1,%2,%3}, {%4,%5,%6,%7}, {%8,%9}, {%0,%1,%2,%3};"
                 : "+f"(d[0]), "+f"(d[1]), "+f"(d[2]), "+f"(d[3])
                 : "r"(a[0]), "r"(a[1]), "r"(a[2]), "r"(a[3]), "r"(b[0]), "r"(b[1]));
}
// f16-accumulator MMA (GEMM1): D regs are f16x2 {c0,c1},{c2,c3}
__device__ __forceinline__ void mma16816hh(uint32_t* d, const uint32_t* a, const uint32_t* b) {
    asm volatile("mma.sync.aligned.m16n8k16.row.col.f16.f16.f16.f16 "
                 "{%0,%1}, {%2,%3,%4,%5}, {%6,%7}, {%0,%1};"
                 : "+r"(d[0]), "+r"(d[1])
                 : "r"(a[0]), "r"(a[1]), "r"(a[2]), "r"(a[3]), "r"(b[0]), "r"(b[1]));
}
__device__ __forceinline__ void red_add_v2(float* p, float a, float b) {
    asm volatile("red.global.add.v2.f32 [%0], {%1, %2};" :: "l"(p), "f"(a), "f"(b) : "memory");
}
__device__ __forceinline__ void red_add_v4(float* p, float a, float b, float c, float d) {
    asm volatile("red.global.add.v4.f32 [%0], {%1, %2, %3, %4};"
                 :: "l"(p), "f"(a), "f"(b), "f"(c), "f"(d) : "memory");
}
__device__ __forceinline__ uint32_t pack_h2(float a, float b) {
    uint32_t p;
    asm("cvt.rn.f16x2.f32 %0, %1, %2;" : "=r"(p) : "f"(b), "f"(a));
    return p;
}
__device__ __forceinline__ float2 unpack_h2(uint32_t p) {
    __half2 h = *reinterpret_cast<__half2*>(&p);
    return __half22float2(h);
}
__device__ __forceinline__ uint32_t hfma2_relu(uint32_t s, uint32_t sc, uint32_t bi) {
    uint32_t d;
    asm("fma.rn.f16x2 %0, %1, %2, %3;" : "=r"(d) : "r"(s), "r"(sc), "r"(bi));
    asm("max.f16x2 %0, %0, %1;" : "+r"(d) : "r"(0u));
    return d;
}

// ---------------------------------------------------------------------------
// prepA: x/rel -> fp16, g_aggr = 0.1x, out = 0
static constexpr int PA_X = N_NODES * (DD / 2);   // 262144 f2 units
static constexpr int PA_R = N_REL * (DD / 2);     // 64000

__global__ void prepA_kernel(const float* __restrict__ x,
                             const float* __restrict__ rel,
                             float* __restrict__ out) {
    int i = blockIdx.x * blockDim.x + threadIdx.x;
    if (i >= PA_X) return;
    float2 v = ((const float2*)x)[i];
    ((uint32_t*)g_xh)[i] = pack_h2(v.x, v.y);
    ((float2*)g_aggr)[i] = make_float2(0.1f * v.x, 0.1f * v.y);
    ((float2*)out)[i] = make_float2(0.f, 0.f);
    if (i < PA_R) {
        float2 r = ((const float2*)rel)[i];
        ((uint32_t*)g_relh)[i] = pack_h2(r.x, r.y);
    }
}

// combo: scatter (blocks [0, SCAT_BLK)) + E/scale/bias fp16 convert (rest)
static constexpr int SCAT_BLK = N_EDGES * 32 / 256;   // 32768
static constexpr int CV_E  = N_ENT * (DD / 2);        // 3,200,000 u32 items
static constexpr int CV_SC = N_ENT / 2;               // 25,000
static constexpr int CV_TOT = CV_E + 2 * CV_SC;       // 3,250,000
static constexpr int CV_BLK = (CV_TOT + 255) / 256;   // 12696

__global__ void combo_kernel(const int* __restrict__ eidx,
                             const int* __restrict__ rid, const int* __restrict__ neg,
                             const float* __restrict__ eemb,
                             const float* __restrict__ scal,
                             const float* __restrict__ bias) {
    if (blockIdx.x < SCAT_BLK) {
        int gw = (blockIdx.x * blockDim.x + threadIdx.x) >> 5;
        int lane = threadIdx.x & 31;
        int src = eidx[gw], dst = eidx[N_EDGES + gw], r = rid[gw];
        float coef = 1.0f - 2.0f * (float)neg[gw];
        uint2 xv = ((const uint2*)(g_xh   + (size_t)src * DD))[lane];
        uint2 rv = ((const uint2*)(g_relh + (size_t)r   * DD))[lane];
        float2 x01 = unpack_h2(xv.x), x23 = unpack_h2(xv.y);
        float2 r01 = unpack_h2(rv.x), r23 = unpack_h2(rv.y);
        red_add_v4(g_aggr + (size_t)dst * DD + lane * 4,
                   (x01.x + r01.x) * coef, (x01.y + r01.y) * coef,
                   (x23.x + r23.x) * coef, (x23.y + r23.y) * coef);
    } else {
        int j = (blockIdx.x - SCAT_BLK) * 256 + threadIdx.x;
        if (j < CV_E) {
            float2 v = ((const float2*)eemb)[j];
            ((uint32_t*)g_Eh)[j] = pack_h2(v.x, v.y);
        } else if (j < CV_E + CV_SC) {
            int k = j - CV_E;
            float2 v = ((const float2*)scal)[k];
            ((uint32_t*)g_sch)[k] = pack_h2(v.x, v.y);
        } else if (j < CV_TOT) {
            int k = j - CV_E - CV_SC;
            float2 v = ((const float2*)bias)[k];
            ((uint32_t*)g_bih)[k] = pack_h2(v.x, v.y);
        }
    }
}

// ---------------------------------------------------------------------------
__global__ void __launch_bounds__(NTHR, 2)
gemm_fused(float* __restrict__ out) {
    extern __shared__ char smem[];
    const uint32_t sb = s2u(smem);
    const int tid = threadIdx.x, wid = tid >> 5, lane = tid & 31;
    const int mt = blockIdx.x & (MTILES - 1), sp = blockIdx.x / MTILES;
    const int m0 = mt * BM;
    const int t0 = sp * TPS, t1 = min(NVT, t0 + TPS);
    if (t0 >= t1) return;

    const int wm = wid * 32;               // warp owns rows [wm, wm+32): 2 m16

    auto load_tiles = [&](int t, int b) {
        const int v0 = t * BV;
        const uint32_t eb = sb + SM_EB + b * EB_STRIDE;
        for (int i = tid; i < 2048; i += NTHR) {    // E [128v,128d] fp16, 16B chunks
            int v = i >> 4, dg = (i & 15) * 8;
            int gv = v0 + v;
            uint32_t o = off128(v, dg);
            int sz = (gv < N_ENT) ? 16 : 0;
            const void* pE = sz ? (const void*)(g_Eh + (size_t)gv * DD + dg) : (const void*)g_Eh;
            cpa16(eb + EB_E + o, pE, sz);
        }
        if (tid < 32) {                              // 128 sc f16 + 128 bi f16
            int half = tid >> 4, g = tid & 15;       // 16 x 16B per array
            int gv = v0 + g * 8;
            int rem = N_ENT - gv;
            int sz = rem >= 8 ? 16 : (rem > 0 ? rem * 2 : 0);
            const __half* src = half ? g_bih : g_sch;
            const void* p = sz ? (const void*)(src + gv) : (const void*)src;
            cpa16(eb + EB_SCB + half * 256 + g * 16, p, sz);
        }
    };

    // issue tile-0 E loads first so they overlap the A staging below
    load_tiles(t0, 0);
    cpa_commit();

    // ---- A tile: g_aggr f32 -> fp16, swizzled (staged once) ----
    for (int i = tid; i < BM * (DD / 4); i += NTHR) {
        int m = i >> 5, k = (i & 31) * 4;
        float4 a = *(const float4*)(g_aggr + (size_t)(m0 + m) * DD + k);
        *(uint32_t*)(smem + SM_A + off128(m, k))     = pack_h2(a.x, a.y);
        *(uint32_t*)(smem + SM_A + off128(m, k + 2)) = pack_h2(a.z, a.w);
    }
    __syncthreads();

    // per-lane ldmatrix pieces (constant across loop)
    const int lr16 = lane & 15;            // row within 16
    const int lc8  = (lane >> 4) << 3;     // +8 col for upper half-warp
    const int lrB  = (lane & 7) | ((lane & 16) >> 1);  // B non-trans row
    const int lcB  = lane & 8;                          // B non-trans col sel
    const int ce   = (lane & 3) * 2;       // C/epilogue col pair base

    float accO[2][16][4];                   // 2 m16 x 128d per warp
    #pragma unroll
    for (int mi = 0; mi < 2; mi++)
        #pragma unroll
        for (int nt = 0; nt < 16; nt++)
            #pragma unroll
            for (int q = 0; q < 4; q++) accO[mi][nt][q] = 0.0f;

    for (int t = t0; t < t1; ++t) {
        const int buf = (t - t0) & 1;
        const uint32_t eb = sb + SM_EB + buf * EB_STRIDE;

        cpa_wait0();           // tile t landed (this thread's copies)
        __syncthreads();       // visible to all; all warps done with buf^1
        if (t + 1 < t1) { load_tiles(t + 1, buf ^ 1); cpa_commit(); }

        // -------- GEMM1: S[32m x 128v] per warp, fp16 accumulators ----------
        // accS[mi][j] covers v-cols [8j, 8j+8)
        uint32_t accS[2][16][2];
        #pragma unroll
        for (int mi = 0; mi < 2; mi++)
            #pragma unroll
            for (int j = 0; j < 16; j++)
                accS[mi][j][0] = accS[mi][j][1] = 0u;

        #pragma unroll
        for (int ks = 0; ks < 8; ks++) {
            const int k0 = ks * 16;
            uint32_t aA[2][4];
            #pragma unroll
            for (int mi = 0; mi < 2; mi++) {
                uint32_t o = off128(wm + mi * 16 + lr16, k0 + lc8);
                ldm4(aA[mi][0], aA[mi][1], aA[mi][2], aA[mi][3], sb + SM_A + o);
            }
            #pragma unroll
            for (int vh = 0; vh < 2; vh++) {
                uint32_t bF[8][2];
                #pragma unroll
                for (int ng = 0; ng < 4; ng++) {
                    uint32_t o = off128(vh * 64 + ng * 16 + lrB, k0 + lcB);
                    uint32_t r0, r1, r2, r3;
                    ldm4(r0, r1, r2, r3, eb + EB_E + o);
                    bF[ng * 2][0] = r0; bF[ng * 2][1] = r1;
                    bF[ng * 2 + 1][0] = r2; bF[ng * 2 + 1][1] = r3;
                }
                #pragma unroll
                for (int mi = 0; mi < 2; mi++)
                    #pragma unroll
                    for (int nt = 0; nt < 8; nt++)
                        mma16816hh(accS[mi][vh * 8 + nt][0] == accS[mi][vh * 8 + nt][0]
                                   ? accS[mi][vh * 8 + nt] : accS[mi][vh * 8 + nt],
                                   aA[mi], bF[nt]);
            }
        }

        // ---- per-g: packed f16x2 epilogue -> GEMM2 for that k16 group ------
        const __half* sch = (const __half*)(smem + SM_EB + buf * EB_STRIDE + EB_SCB);
        #pragma unroll
        for (int g = 0; g < 8; g++) {
            uint32_t aS[2][4];
            #pragma unroll
            for (int sub2 = 0; sub2 < 2; sub2++) {      // j = 2g, 2g+1
                const int j = 2 * g + sub2;
                const int c = j * 8 + ce;
                uint32_t sc2 = *(const uint32_t*)(sch + c);
                uint32_t bi2 = *(const uint32_t*)(sch + 128 + c);
                #pragma unroll
                for (int mi = 0; mi < 2; mi++) {
                    aS[mi][sub2 * 2]     = hfma2_relu(accS[mi][j][0], sc2, bi2);
                    aS[mi][sub2 * 2 + 1] = hfma2_relu(accS[mi][j][1], sc2, bi2);
                }
            }
            const int k0 = g * 16;
            #pragma unroll
            for (int half = 0; half < 2; half++) {
                uint32_t bF[8][2];
                #pragma unroll
                for (int ng = 0; ng < 4; ng++) {
                    uint32_t o = off128(k0 + lr16, half * 64 + ng * 16 + lc8);
                    uint32_t r0, r1, r2, r3;
                    ldm4t(r0, r1, r2, r3, eb + EB_E + o);
                    bF[ng * 2][0] = r0; bF[ng * 2][1] = r1;
                    bF[ng * 2 + 1][0] = r2; bF[ng * 2 + 1][1] = r3;
                }
                #pragma unroll
                for (int mi = 0; mi < 2; mi++)
                    #pragma unroll
                    for (int ng = 0; ng < 8; ng++)
                        mma16816h(accO[mi][half * 8 + ng], aS[mi], bF[ng]);
            }
        }
    }

    // ---- flush O to out (+= across splits) ----
    #pragma unroll
    for (int mi = 0; mi < 2; mi++) {
        const int r0 = m0 + wm + mi * 16 + (lane >> 2);
        #pragma unroll
        for (int nt = 0; nt < 16; nt++) {
            const int c = nt * 8 + ce;
            red_add_v2(out + (size_t)r0 * DD + c,       accO[mi][nt][0], accO[mi][nt][1]);
            red_add_v2(out + (size_t)(r0 + 8) * DD + c, accO[mi][nt][2], accO[mi][nt][3]);
        }
    }
}

// ---------------------------------------------------------------------------
extern "C" void kernel_launch(void* const* d_in, const int* in_sizes, int n_in,
                              void* d_out, int out_size) {
    const float* x     = (const float*)d_in[0];
    const int*   eidx  = (const int*)  d_in[1];
    const int*   rid   = (const int*)  d_in[2];
    const int*   neg   = (const int*)  d_in[3];
    const float* rel   = (const float*)d_in[4];
    const float* eemb  = (const float*)d_in[5];
    const float* scale = (const float*)d_in[6];
    const float* bias  = (const float*)d_in[7];
    float* out = (float*)d_out;

    cudaFuncSetAttribute(gemm_fused, cudaFuncAttributeMaxDynamicSharedMemorySize, SMEM_BYTES);

    prepA_kernel<<<(PA_X + 255) / 256, 256>>>(x, rel, out);
    combo_kernel<<<SCAT_BLK + CV_BLK, 256>>>(eidx, rid, neg, eemb, scale, bias);
    gemm_fused<<<MTILES * NSPLIT, NTHR, SMEM_BYTES>>>(out);
}